// round 12
// baseline (speedup 1.0000x reference)
#include <cuda_runtime.h>
#include <cuda_bf16.h>
#include <cstdint>

#define NN 100000
#define EE 400000
#define KKk 2
#define DD 256
#define ATTD 64
#define LLn 3
#define HH1 128
#define HH2 64
#define KN (KKk*NN)
#define KE (KKk*EE)
#define EPSF 1e-5f
#define SLOPE 0.01f
#define NB_SCAN ((KN + 1023) / 1024)

// ----------------------------------------------------------------------------
// Scratch (static device globals)
// ----------------------------------------------------------------------------
__device__ __nv_bfloat16 g_hhi[(size_t)NN * DD];
__device__ __nv_bfloat16 g_hlo[(size_t)NN * DD];
__device__ __nv_bfloat16 g_xwhi[(size_t)NN * DD];
__device__ __nv_bfloat16 g_xwlo[(size_t)NN * DD];
__device__ __nv_bfloat16 g_xshi[(size_t)KKk * NN * DD];
__device__ __nv_bfloat16 g_xslo[(size_t)KKk * NN * DD];
__device__ __nv_bfloat16 g_t1hi[(size_t)NN * HH1];
__device__ __nv_bfloat16 g_t1lo[(size_t)NN * HH1];
__device__ float g_sim[KN];
__device__ float g_sum[DD];
__device__ float g_sq[DD];
__device__ float g_scale[DD];
__device__ float g_shift[DD];
__device__ float g_deg[KN];
__device__ float g_dinv[KN];
__device__ int   g_cnt[KN];
__device__ int   g_ptr[KN];
__device__ int   g_fill[KN];
__device__ int   g_scn[KN];
__device__ int   g_bsum[256];
__device__ int   g_rowS[KE];
__device__ float g_normS[KE];

// Transposed + bf16-split weights, [n][k] layout.
#define WOFF_GCN(i)    ((size_t)(i) * 65536)
#define WOFF_ATT(i, k) (196608u + (size_t)((i) * 2 + (k)) * 16384)
#define WOFF_P1        294912u
#define WOFF_P2        327680u
#define WT_TOT 335872
__device__ __nv_bfloat16 g_whi[WT_TOT];
__device__ __nv_bfloat16 g_wlo[WT_TOT];

// ----------------------------------------------------------------------------
// PTX helpers
// ----------------------------------------------------------------------------
__device__ __forceinline__ uint32_t smem_u32(const void* p) {
    uint32_t a;
    asm("{ .reg .u64 t; cvta.to.shared.u64 t, %1; cvt.u32.u64 %0, t; }"
        : "=r"(a) : "l"(p));
    return a;
}
__device__ __forceinline__ void ldsm4(uint32_t* r, uint32_t addr) {
    asm volatile("ldmatrix.sync.aligned.m8n8.x4.shared.b16 {%0,%1,%2,%3},[%4];"
                 : "=r"(r[0]), "=r"(r[1]), "=r"(r[2]), "=r"(r[3]) : "r"(addr));
}
__device__ __forceinline__ void mma16816(float* c, const uint32_t* a, const uint32_t* b) {
    asm volatile(
        "mma.sync.aligned.m16n8k16.row.col.f32.bf16.bf16.f32 "
        "{%0,%1,%2,%3},{%4,%5,%6,%7},{%8,%9},{%0,%1,%2,%3};"
        : "+f"(c[0]), "+f"(c[1]), "+f"(c[2]), "+f"(c[3])
        : "r"(a[0]), "r"(a[1]), "r"(a[2]), "r"(a[3]), "r"(b[0]), "r"(b[1]));
}
__device__ __forceinline__ void cpa16(uint32_t dst, const void* src) {
    asm volatile("cp.async.cg.shared.global [%0], [%1], 16;" :: "r"(dst), "l"(src));
}
__device__ __forceinline__ void cpa_commit() {
    asm volatile("cp.async.commit_group;" ::: "memory");
}
template <int Nw>
__device__ __forceinline__ void cpa_wait() {
    asm volatile("cp.async.wait_group %0;" :: "n"(Nw) : "memory");
}
__device__ __forceinline__ void split_bf16(float v, __nv_bfloat16& h, __nv_bfloat16& l) {
    h = __float2bfloat16(v);
    l = __float2bfloat16(v - __bfloat162float(h));
}
// L2 policies (createpolicy; any-width via cache_hint on BOTH ld and st)
__device__ __forceinline__ uint64_t pol_evl() {
    uint64_t p;
    asm("createpolicy.fractional.L2::evict_last.b64 %0, 1.0;" : "=l"(p));
    return p;
}
__device__ __forceinline__ uint64_t pol_evf() {
    uint64_t p;
    asm("createpolicy.fractional.L2::evict_first.b64 %0, 1.0;" : "=l"(p));
    return p;
}
__device__ __forceinline__ uint4 ldg_pol128(const void* p, uint64_t pol) {
    uint4 v;
    asm volatile("ld.global.L2::cache_hint.v4.u32 {%0,%1,%2,%3}, [%4], %5;"
                 : "=r"(v.x), "=r"(v.y), "=r"(v.z), "=r"(v.w)
                 : "l"(p), "l"(pol));
    return v;
}
__device__ __forceinline__ uint2 ldg_pol64(const void* p, uint64_t pol) {
    uint2 v;
    asm volatile("ld.global.L2::cache_hint.v2.u32 {%0,%1}, [%2], %3;"
                 : "=r"(v.x), "=r"(v.y) : "l"(p), "l"(pol));
    return v;
}
__device__ __forceinline__ void stg_pol128(void* p, uint4 v, uint64_t pol) {
    asm volatile("st.global.L2::cache_hint.v4.u32 [%0], {%1,%2,%3,%4}, %5;"
                 :: "l"(p), "r"(v.x), "r"(v.y), "r"(v.z), "r"(v.w), "l"(pol)
                 : "memory");
}
__device__ __forceinline__ void stg_pol64(void* p, uint2 v, uint64_t pol) {
    asm volatile("st.global.L2::cache_hint.v2.u32 [%0], {%1,%2}, %3;"
                 :: "l"(p), "r"(v.x), "r"(v.y), "l"(pol) : "memory");
}
__device__ __forceinline__ void stg_pol32(void* p, uint32_t v, uint64_t pol) {
    asm volatile("st.global.L2::cache_hint.u32 [%0], %1, %2;"
                 :: "l"(p), "r"(v), "l"(pol) : "memory");
}

// ----------------------------------------------------------------------------
// Fused zero kernel
// ----------------------------------------------------------------------------
__global__ void k_zero_all() {
    int i = blockIdx.x * blockDim.x + threadIdx.x;
    if (i < KN) { g_deg[i] = 0.f; g_cnt[i] = 0; g_fill[i] = 0; }
    if (i < DD) { g_sum[i] = 0.f; g_sq[i] = 0.f; }
}

// ----------------------------------------------------------------------------
// Fused weight transpose + bf16 split
// ----------------------------------------------------------------------------
__global__ void k_wsplit_all(const float* __restrict__ gcnW,
                             const float* __restrict__ attW,
                             const float* __restrict__ pW1,
                             const float* __restrict__ pW2) {
    int i = blockIdx.x * blockDim.x + threadIdx.x;
    if (i >= WT_TOT) return;
    const float* src;
    int rem, Kd, Nd, base;
    if (i < 196608) {
        int m = i >> 16; rem = i & 65535;
        src = gcnW + (size_t)m * 65536; Kd = 256; Nd = 256; base = m * 65536;
    } else if (i < 294912) {
        int j = (i - 196608) >> 14; rem = (i - 196608) & 16383;
        src = attW + (size_t)j * 16384; Kd = 256; Nd = 64; base = 196608 + j * 16384;
    } else if (i < 327680) {
        rem = i - 294912; src = pW1; Kd = 256; Nd = 128; base = 294912;
    } else {
        rem = i - 327680; src = pW2; Kd = 128; Nd = 64; base = 327680;
    }
    int k = rem / Nd, n = rem - k * Nd;
    float v = src[rem];
    __nv_bfloat16 h, l;
    split_bf16(v, h, l);
    g_whi[base + n * Kd + k] = h;
    g_wlo[base + n * Kd + k] = l;
}

// ----------------------------------------------------------------------------
// BatchNorm: colstats -> fin (scale/shift) -> bn (2 vector loads/thread)
// ----------------------------------------------------------------------------
__global__ void k_colstats(const float* __restrict__ x) {
    int d = threadIdx.x;
    float s = 0.f, q = 0.f;
    for (int r = blockIdx.x; r < NN; r += gridDim.x) {
        float v = x[(size_t)r * DD + d];
        s += v;
        q += v * v;
    }
    atomicAdd(&g_sum[d], s);
    atomicAdd(&g_sq[d], q);
}
__global__ void k_fin(const float* __restrict__ gamma, const float* __restrict__ beta) {
    int d = threadIdx.x;
    float mu  = g_sum[d] * (1.f / NN);
    float var = g_sq[d] * (1.f / NN) - mu * mu;
    float istd = rsqrtf(var + EPSF);
    float sc = istd * gamma[d];
    g_scale[d] = sc;
    g_shift[d] = beta[d] - mu * sc;
}
__global__ void k_bn(const float* __restrict__ x) {
    int i = blockIdx.x * blockDim.x + threadIdx.x;
    if (i >= NN * DD / 4) return;
    uint64_t pl = pol_evl();
    int d = (i & 63) * 4;
    float4 v = ((const float4*)x)[i];
    float4 sc = *(const float4*)(g_scale + d);
    float4 sh = *(const float4*)(g_shift + d);
    float f[4];
    f[0] = v.x * sc.x + sh.x;
    f[1] = v.y * sc.y + sh.y;
    f[2] = v.z * sc.z + sh.z;
    f[3] = v.w * sc.w + sh.w;
    __nv_bfloat16 h[4], l[4];
#pragma unroll
    for (int j = 0; j < 4; j++) split_bf16(f[j], h[j], l[j]);
    stg_pol64(g_hhi + (size_t)i * 4, *(uint2*)h, pl);
    stg_pol64(g_hlo + (size_t)i * 4, *(uint2*)l, pl);
}

// ----------------------------------------------------------------------------
// CSR build
// ----------------------------------------------------------------------------
__global__ void k_degcnt(const int* __restrict__ ei, const float* __restrict__ ew) {
    int i = blockIdx.x * blockDim.x + threadIdx.x;
    if (i >= KE) return;
    int k = i / EE, e = i - k * EE;
    int col = ei[(size_t)k * 2 * EE + EE + e];
    float w = ew[i];
    atomicAdd(&g_deg[k * NN + col], w);
    atomicAdd(&g_cnt[k * NN + col], 1);
}
__global__ void k_scan1() {
    __shared__ int s[1024];
    int t = threadIdx.x;
    int i = blockIdx.x * 1024 + t;
    if (i < KN) {
        float d = g_deg[i];
        g_dinv[i] = d > 0.f ? rsqrtf(d) : 0.f;
    }
    s[t] = (i < KN) ? g_cnt[i] : 0;
    __syncthreads();
    for (int off = 1; off < 1024; off <<= 1) {
        int u = (t >= off) ? s[t - off] : 0;
        __syncthreads();
        s[t] += u;
        __syncthreads();
    }
    if (i < KN) g_scn[i] = s[t];
    if (t == 1023) g_bsum[blockIdx.x] = s[1023];
}
__global__ void k_scan3(int nb) {
    __shared__ int sb[256];
    __shared__ int sOff;
    int t = threadIdx.x;
    if (t < nb) sb[t] = g_bsum[t];
    __syncthreads();
    if (t == 0) {
        int run = 0;
        for (int b = 0; b < (int)blockIdx.x; b++) run += sb[b];
        sOff = run;
    }
    __syncthreads();
    int i = blockIdx.x * 1024 + t;
    if (i >= KN) return;
    g_ptr[i] = g_scn[i] - g_cnt[i] + sOff;
}
__global__ void k_scatter(const int* __restrict__ ei, const float* __restrict__ ew) {
    int i = blockIdx.x * blockDim.x + threadIdx.x;
    if (i >= KE) return;
    int k = i / EE, e = i - k * EE;
    int row = ei[(size_t)k * 2 * EE + e];
    int col = ei[(size_t)k * 2 * EE + EE + e];
    float w = ew[i];
    int b = k * NN + col;
    int p = g_ptr[b] + atomicAdd(&g_fill[b], 1);
    g_rowS[p]  = row;
    g_normS[p] = g_dinv[b] * w * g_dinv[k * NN + row];
}

// ----------------------------------------------------------------------------
// Gather aggregation, column-split: grid.y selects feature half so the pass
// working set (50MB hi + 50MB lo) FITS L2. One warp per (k,node), 4 feats/lane.
// ----------------------------------------------------------------------------
__global__ void k_aggregate(const float* __restrict__ bias) {
    int node = (blockIdx.x * blockDim.x + threadIdx.x) >> 5;
    int lane = threadIdx.x & 31;
    if (node >= KN) return;
    uint64_t pf = pol_evf();
    uint64_t pl = pol_evl();
    int s = g_ptr[node], c = g_cnt[node];
    float a[4] = {0.f, 0.f, 0.f, 0.f};
    int co = blockIdx.y * 128 + lane * 4;
    int e = 0;
    for (; e + 2 <= c; e += 2) {
        int r0 = g_rowS[s + e], r1 = g_rowS[s + e + 1];
        float nv0 = g_normS[s + e], nv1 = g_normS[s + e + 1];
        uint2 h0 = ldg_pol64(g_xwhi + (size_t)r0 * DD + co, pl);
        uint2 l0 = ldg_pol64(g_xwlo + (size_t)r0 * DD + co, pl);
        uint2 h1 = ldg_pol64(g_xwhi + (size_t)r1 * DD + co, pl);
        uint2 l1 = ldg_pol64(g_xwlo + (size_t)r1 * DD + co, pl);
        const __nv_bfloat16* hp0 = (const __nv_bfloat16*)&h0;
        const __nv_bfloat16* lp0 = (const __nv_bfloat16*)&l0;
        const __nv_bfloat16* hp1 = (const __nv_bfloat16*)&h1;
        const __nv_bfloat16* lp1 = (const __nv_bfloat16*)&l1;
#pragma unroll
        for (int j = 0; j < 4; j++) {
            a[j] += nv0 * (__bfloat162float(hp0[j]) + __bfloat162float(lp0[j]));
            a[j] += nv1 * (__bfloat162float(hp1[j]) + __bfloat162float(lp1[j]));
        }
    }
    if (e < c) {
        int r = g_rowS[s + e];
        float nv = g_normS[s + e];
        uint2 hv = ldg_pol64(g_xwhi + (size_t)r * DD + co, pl);
        uint2 lv = ldg_pol64(g_xwlo + (size_t)r * DD + co, pl);
        const __nv_bfloat16* hp = (const __nv_bfloat16*)&hv;
        const __nv_bfloat16* lp = (const __nv_bfloat16*)&lv;
#pragma unroll
        for (int j = 0; j < 4; j++)
            a[j] += nv * (__bfloat162float(hp[j]) + __bfloat162float(lp[j]));
    }
    float4 b4 = *(const float4*)(bias + co);
    a[0] += b4.x; a[1] += b4.y; a[2] += b4.z; a[3] += b4.w;
    __nv_bfloat16 ho[4], lo[4];
#pragma unroll
    for (int j = 0; j < 4; j++) split_bf16(a[j], ho[j], lo[j]);
    stg_pol64(g_xshi + (size_t)node * DD + co, *(uint2*)ho, pf);
    stg_pol64(g_xslo + (size_t)node * DD + co, *(uint2*)lo, pf);
}

// ----------------------------------------------------------------------------
// HMMA split-bf16 GEMM, cp.async double-buffered
// ----------------------------------------------------------------------------
template <int BN_, int NOUT, int KDIM, int ACT, int OSPLIT>
__global__ void __launch_bounds__(256, 2) hmma_gemm(
    const __nv_bfloat16* __restrict__ Ahi, const __nv_bfloat16* __restrict__ Alo,
    const __nv_bfloat16* __restrict__ Bhi, const __nv_bfloat16* __restrict__ Blo,
    const float* __restrict__ bias, float* __restrict__ C,
    __nv_bfloat16* __restrict__ Chi, __nv_bfloat16* __restrict__ Clo, int M)
{
    constexpr int LDA = 40;
    constexpr int WN = BN_ / 2;
    constexpr int NT = WN / 8;
    constexpr int NC = KDIM / 32;
    constexpr int ABYTES = 128 * LDA * 2;
    constexpr int BOFF   = 2 * ABYTES;
    constexpr int BBYTES = BN_ * LDA * 2;
    constexpr int SSTAGE = BOFF + 2 * BBYTES;
    extern __shared__ char dynsm[];
    uint32_t smBase = smem_u32(dynsm);

    int tid = threadIdx.x, wid = tid >> 5, lane = tid & 31;
    int warpM = wid & 3, warpN = wid >> 2;
    int row0 = blockIdx.x * 128;
    int colBase = blockIdx.y * BN_;

    float acc[2][NT][4];
#pragma unroll
    for (int mt = 0; mt < 2; mt++)
#pragma unroll
        for (int nt = 0; nt < NT; nt++)
#pragma unroll
            for (int q = 0; q < 4; q++) acc[mt][nt][q] = 0.f;

    auto load_stage = [&](int kc, uint32_t sb) {
        constexpr int TOT = 1024 + 8 * BN_;
#pragma unroll
        for (int c = tid; c < TOT; c += 256) {
            const __nv_bfloat16* src;
            uint32_t dst;
            if (c < 1024) {
                int mat = c >> 9;
                int cc = c & 511;
                int r = cc >> 2, col = (cc & 3) << 3;
                int gr = row0 + r;
                gr = gr < M ? gr : (M - 1);
                src = (mat ? Alo : Ahi) + (size_t)gr * KDIM + kc * 32 + col;
                dst = sb + mat * ABYTES + (uint32_t)(r * LDA + col) * 2;
            } else {
                int c2 = c - 1024;
                int mat = c2 / (BN_ * 4);
                int cc = c2 % (BN_ * 4);
                int r = cc >> 2, col = (cc & 3) << 3;
                src = (mat ? Blo : Bhi) + (size_t)(colBase + r) * KDIM + kc * 32 + col;
                dst = sb + BOFF + mat * BBYTES + (uint32_t)(r * LDA + col) * 2;
            }
            cpa16(dst, src);
        }
        cpa_commit();
    };

    load_stage(0, smBase);
    for (int kc = 0; kc < NC; kc++) {
        if (kc + 1 < NC) {
            load_stage(kc + 1, smBase + (uint32_t)((kc + 1) & 1) * SSTAGE);
            cpa_wait<1>();
        } else {
            cpa_wait<0>();
        }
        __syncthreads();
        uint32_t st = smBase + (uint32_t)(kc & 1) * SSTAGE;
        uint32_t uAhi = st, uAlo = st + ABYTES;
        uint32_t uBhi = st + BOFF, uBlo = st + BOFF + BBYTES;

#pragma unroll
        for (int ks = 0; ks < 2; ks++) {
            uint32_t ahi[2][4], alo[2][4];
#pragma unroll
            for (int mt = 0; mt < 2; mt++) {
                uint32_t aoff =
                    ((warpM * 32 + mt * 16 + (lane & 15)) * LDA + (lane >> 4) * 8 + ks * 16) * 2;
                ldsm4(ahi[mt], uAhi + aoff);
                ldsm4(alo[mt], uAlo + aoff);
            }
            uint32_t bhi[NT][2], blo[NT][2];
#pragma unroll
            for (int p = 0; p < NT / 2; p++) {
                int nrow = warpN * WN + p * 16 + (lane & 7) + ((lane & 16) >> 1);
                int kcol = ks * 16 + (lane & 8);
                uint32_t boff = (uint32_t)(nrow * LDA + kcol) * 2;
                uint32_t t[4];
                ldsm4(t, uBhi + boff);
                bhi[2 * p][0] = t[0]; bhi[2 * p][1] = t[1];
                bhi[2 * p + 1][0] = t[2]; bhi[2 * p + 1][1] = t[3];
                ldsm4(t, uBlo + boff);
                blo[2 * p][0] = t[0]; blo[2 * p][1] = t[1];
                blo[2 * p + 1][0] = t[2]; blo[2 * p + 1][1] = t[3];
            }
#pragma unroll
            for (int mt = 0; mt < 2; mt++)
#pragma unroll
                for (int nt = 0; nt < NT; nt++) {
                    mma16816(acc[mt][nt], ahi[mt], bhi[nt]);
                    mma16816(acc[mt][nt], ahi[mt], blo[nt]);
                    mma16816(acc[mt][nt], alo[mt], bhi[nt]);
                }
        }
        __syncthreads();
    }

    uint64_t pl = pol_evl();
#pragma unroll
    for (int mt = 0; mt < 2; mt++) {
        int row = row0 + warpM * 32 + mt * 16 + (lane >> 2);
#pragma unroll
        for (int nt = 0; nt < NT; nt++) {
            int col = colBase + warpN * WN + nt * 8 + (lane & 3) * 2;
            float b0 = 0.f, b1 = 0.f;
            if (bias) { b0 = bias[col]; b1 = bias[col + 1]; }
            float v0 = acc[mt][nt][0] + b0, v1 = acc[mt][nt][1] + b1;
            float v2 = acc[mt][nt][2] + b0, v3 = acc[mt][nt][3] + b1;
            if (ACT == 1) {
                v0 = v0 > 0.f ? v0 : SLOPE * v0; v1 = v1 > 0.f ? v1 : SLOPE * v1;
                v2 = v2 > 0.f ? v2 : SLOPE * v2; v3 = v3 > 0.f ? v3 : SLOPE * v3;
            }
            if (OSPLIT) {
                __nv_bfloat16 h0, l0, h1, l1;
                if (row < M) {
                    split_bf16(v0, h0, l0); split_bf16(v1, h1, l1);
                    __nv_bfloat16 hp[2] = {h0, h1}, lp[2] = {l0, l1};
                    stg_pol32(Chi + (size_t)row * NOUT + col, *(uint32_t*)hp, pl);
                    stg_pol32(Clo + (size_t)row * NOUT + col, *(uint32_t*)lp, pl);
                }
                if (row + 8 < M) {
                    split_bf16(v2, h0, l0); split_bf16(v3, h1, l1);
                    __nv_bfloat16 hp[2] = {h0, h1}, lp[2] = {l0, l1};
                    stg_pol32(Chi + (size_t)(row + 8) * NOUT + col, *(uint32_t*)hp, pl);
                    stg_pol32(Clo + (size_t)(row + 8) * NOUT + col, *(uint32_t*)lp, pl);
                }
            } else {
                if (row < M)
                    *(float2*)(C + (size_t)row * NOUT + col) = make_float2(v0, v1);
                if (row + 8 < M)
                    *(float2*)(C + (size_t)(row + 8) * NOUT + col) = make_float2(v2, v3);
            }
        }
    }
}

// ----------------------------------------------------------------------------
// Attention GEMM with fused sim epilogue
// ----------------------------------------------------------------------------
__global__ void __launch_bounds__(256, 2) hmma_att(
    const __nv_bfloat16* __restrict__ AhiB, const __nv_bfloat16* __restrict__ AloB,
    const __nv_bfloat16* __restrict__ BhiB, const __nv_bfloat16* __restrict__ BloB,
    const float* __restrict__ biasB, const float* __restrict__ qB,
    float* __restrict__ simB, int M)
{
    constexpr int LDA = 40, NC = 8;
    constexpr int ABYTES = 128 * LDA * 2;
    constexpr int BOFF = 2 * ABYTES;
    constexpr int BBYTES = 64 * LDA * 2;
    constexpr int SSTAGE = BOFF + 2 * BBYTES;
    extern __shared__ char dynsm[];
    uint32_t smBase = smem_u32(dynsm);

    int tid = threadIdx.x, wid = tid >> 5, lane = tid & 31;
    int row0 = blockIdx.x * 128;
    int kk = blockIdx.z;
    const __nv_bfloat16* Ahi = AhiB + (size_t)kk * NN * DD;
    const __nv_bfloat16* Alo = AloB + (size_t)kk * NN * DD;
    const __nv_bfloat16* Bhi = BhiB + (size_t)kk * 16384;
    const __nv_bfloat16* Blo = BloB + (size_t)kk * 16384;
    const float* bias = biasB + kk * ATTD;
    const float* q    = qB + kk * ATTD;
    float* sim        = simB + (size_t)kk * NN;

    float acc[8][4];
#pragma unroll
    for (int nt = 0; nt < 8; nt++)
#pragma unroll
        for (int p = 0; p < 4; p++) acc[nt][p] = 0.f;

    auto load_stage = [&](int kc, uint32_t sb) {
        constexpr int TOT = 1024 + 512;
#pragma unroll
        for (int c = tid; c < TOT; c += 256) {
            const __nv_bfloat16* src;
            uint32_t dst;
            if (c < 1024) {
                int mat = c >> 9;
                int cc = c & 511;
                int r = cc >> 2, col = (cc & 3) << 3;
                int gr = row0 + r;
                gr = gr < M ? gr : (M - 1);
                src = (mat ? Alo : Ahi) + (size_t)gr * DD + kc * 32 + col;
                dst = sb + mat * ABYTES + (uint32_t)(r * LDA + col) * 2;
            } else {
                int c2 = c - 1024;
                int mat = c2 >> 8;
                int cc = c2 & 255;
                int r = cc >> 2, col = (cc & 3) << 3;
                src = (mat ? Blo : Bhi) + (size_t)r * DD + kc * 32 + col;
                dst = sb + BOFF + mat * BBYTES + (uint32_t)(r * LDA + col) * 2;
            }
            cpa16(dst, src);
        }
        cpa_commit();
    };

    load_stage(0, smBase);
    for (int kc = 0; kc < NC; kc++) {
        if (kc + 1 < NC) {
            load_stage(kc + 1, smBase + (uint32_t)((kc + 1) & 1) * SSTAGE);
            cpa_wait<1>();
        } else {
            cpa_wait<0>();
        }
        __syncthreads();
        uint32_t st = smBase + (uint32_t)(kc & 1) * SSTAGE;
        uint32_t uAhi = st, uAlo = st + ABYTES;
        uint32_t uBhi = st + BOFF, uBlo = st + BOFF + BBYTES;

#pragma unroll
        for (int ks = 0; ks < 2; ks++) {
            uint32_t ahi[4], alo[4];
            uint32_t aoff =
                ((wid * 16 + (lane & 15)) * LDA + (lane >> 4) * 8 + ks * 16) * 2;
            ldsm4(ahi, uAhi + aoff);
            ldsm4(alo, uAlo + aoff);
            uint32_t bhi[8][2], blo[8][2];
#pragma unroll
            for (int p = 0; p < 4; p++) {
                int nrow = p * 16 + (lane & 7) + ((lane & 16) >> 1);
                int kcol = ks * 16 + (lane & 8);
                uint32_t boff = (uint32_t)(nrow * LDA + kcol) * 2;
                uint32_t t[4];
                ldsm4(t, uBhi + boff);
                bhi[2 * p][0] = t[0]; bhi[2 * p][1] = t[1];
                bhi[2 * p + 1][0] = t[2]; bhi[2 * p + 1][1] = t[3];
                ldsm4(t, uBlo + boff);
                blo[2 * p][0] = t[0]; blo[2 * p][1] = t[1];
                blo[2 * p + 1][0] = t[2]; blo[2 * p + 1][1] = t[3];
            }
#pragma unroll
            for (int nt = 0; nt < 8; nt++) {
                mma16816(acc[nt], ahi, bhi[nt]);
                mma16816(acc[nt], ahi, blo[nt]);
                mma16816(acc[nt], alo, bhi[nt]);
            }
        }
        __syncthreads();
    }

    float t0 = 0.f, t1 = 0.f;
#pragma unroll
    for (int nt = 0; nt < 8; nt++) {
        int col = nt * 8 + (lane & 3) * 2;
        float b0 = bias[col], b1 = bias[col + 1];
        float q0 = q[col], q1 = q[col + 1];
        t0 += tanhf(acc[nt][0] + b0) * q0 + tanhf(acc[nt][1] + b1) * q1;
        t1 += tanhf(acc[nt][2] + b0) * q0 + tanhf(acc[nt][3] + b1) * q1;
    }
    t0 += __shfl_xor_sync(0xffffffffu, t0, 1);
    t0 += __shfl_xor_sync(0xffffffffu, t0, 2);
    t1 += __shfl_xor_sync(0xffffffffu, t1, 1);
    t1 += __shfl_xor_sync(0xffffffffu, t1, 2);
    if ((lane & 3) == 0) {
        int row = row0 + wid * 16 + (lane >> 2);
        if (row < M) sim[row] = t0;
        if (row + 8 < M) sim[row + 8] = t1;
    }
}

// ----------------------------------------------------------------------------
// Softmax over K + combine + relu
// ----------------------------------------------------------------------------
__global__ void k_combine() {
    int node = (blockIdx.x * blockDim.x + threadIdx.x) >> 5;
    int lane = threadIdx.x & 31;
    if (node >= NN) return;
    uint64_t pl = pol_evl();
    uint64_t pf = pol_evf();
    float p0 = g_sim[node], p1 = g_sim[NN + node];
    float m = fmaxf(p0, p1);
    float e0 = expf(p0 - m), e1 = expf(p1 - m);
    float inv = 1.f / (e0 + e1);
    float a0v = e0 * inv, a1v = e1 * inv;
    size_t off = (size_t)node * DD + lane * 8;
    uint4 h0 = ldg_pol128(g_xshi + off, pf);
    uint4 l0 = ldg_pol128(g_xslo + off, pf);
    uint4 h1 = ldg_pol128(g_xshi + (size_t)NN * DD + off, pf);
    uint4 l1 = ldg_pol128(g_xslo + (size_t)NN * DD + off, pf);
    const __nv_bfloat16* ph0 = (const __nv_bfloat16*)&h0;
    const __nv_bfloat16* pl0 = (const __nv_bfloat16*)&l0;
    const __nv_bfloat16* ph1 = (const __nv_bfloat16*)&h1;
    const __nv_bfloat16* pl1 = (const __nv_bfloat16*)&l1;
    __nv_bfloat16 oh[8], ol[8];
#pragma unroll
    for (int j = 0; j < 8; j++) {
        float f0 = __bfloat162float(ph0[j]) + __bfloat162float(pl0[j]);
        float f1 = __bfloat162float(ph1[j]) + __bfloat162float(pl1[j]);
        float r = fmaxf(a0v * f0 + a1v * f1, 0.f);
        split_bf16(r, oh[j], ol[j]);
    }
    stg_pol128(g_hhi + off, *(uint4*)oh, pl);
    stg_pol128(g_hlo + off, *(uint4*)ol, pl);
}

// ----------------------------------------------------------------------------
// Host orchestration
// ----------------------------------------------------------------------------
extern "C" void kernel_launch(void* const* d_in, const int* in_sizes, int n_in,
                              void* d_out, int out_size) {
    const float* x     = (const float*)d_in[0];
    const int*   ei    = (const int*)d_in[1];
    const float* ew    = (const float*)d_in[2];
    const float* gamma = (const float*)d_in[3];
    const float* beta  = (const float*)d_in[4];
    const float* gcnW  = (const float*)d_in[5];
    const float* gcnb  = (const float*)d_in[6];
    const float* attW  = (const float*)d_in[7];
    const float* attb  = (const float*)d_in[8];
    const float* attq  = (const float*)d_in[9];
    const float* pW1   = (const float*)d_in[10];
    const float* pb1   = (const float*)d_in[11];
    const float* pW2   = (const float*)d_in[12];
    const float* pb2   = (const float*)d_in[13];

    float *pSim;
    __nv_bfloat16 *pWhi, *pWlo, *pHhi, *pHlo, *pXwhi, *pXwlo, *pXshi, *pXslo,
                  *pT1hi, *pT1lo;
    cudaGetSymbolAddress((void**)&pSim, g_sim);
    cudaGetSymbolAddress((void**)&pWhi, g_whi);
    cudaGetSymbolAddress((void**)&pWlo, g_wlo);
    cudaGetSymbolAddress((void**)&pHhi, g_hhi);
    cudaGetSymbolAddress((void**)&pHlo, g_hlo);
    cudaGetSymbolAddress((void**)&pXwhi, g_xwhi);
    cudaGetSymbolAddress((void**)&pXwlo, g_xwlo);
    cudaGetSymbolAddress((void**)&pXshi, g_xshi);
    cudaGetSymbolAddress((void**)&pXslo, g_xslo);
    cudaGetSymbolAddress((void**)&pT1hi, g_t1hi);
    cudaGetSymbolAddress((void**)&pT1lo, g_t1lo);

    cudaFuncSetAttribute((const void*)hmma_gemm<128, 256, 256, 0, 1>,
                         cudaFuncAttributeMaxDynamicSharedMemorySize, 81920);
    cudaFuncSetAttribute((const void*)hmma_att,
                         cudaFuncAttributeMaxDynamicSharedMemorySize, 61440);
    cudaFuncSetAttribute((const void*)hmma_gemm<128, 128, 256, 1, 1>,
                         cudaFuncAttributeMaxDynamicSharedMemorySize, 81920);
    cudaFuncSetAttribute((const void*)hmma_gemm<64, 64, 128, 1, 0>,
                         cudaFuncAttributeMaxDynamicSharedMemorySize, 61440);

    k_zero_all<<<(KN + 255) / 256, 256>>>();
    k_wsplit_all<<<(WT_TOT + 255) / 256, 256>>>(gcnW, attW, pW1, pW2);

    k_colstats<<<512, 256>>>(x);
    k_fin<<<1, 256>>>(gamma, beta);
    k_bn<<<(NN * DD / 4 + 255) / 256, 256>>>(x);

    k_degcnt<<<(KE + 255) / 256, 256>>>(ei, ew);
    k_scan1<<<NB_SCAN, 1024>>>();
    k_scan3<<<NB_SCAN, 1024>>>(NB_SCAN);
    k_scatter<<<(KE + 255) / 256, 256>>>(ei, ew);

    int nTiles = (NN + 127) / 128;

    for (int i = 0; i < LLn; i++) {
        hmma_gemm<128, 256, 256, 0, 1><<<dim3(nTiles, 2), 256, 81920>>>(
            pHhi, pHlo, pWhi + WOFF_GCN(i), pWlo + WOFF_GCN(i),
            nullptr, nullptr, pXwhi, pXwlo, NN);
        k_aggregate<<<dim3((KN + 7) / 8, 2), 256>>>(gcnb + (size_t)i * DD);
        hmma_att<<<dim3(nTiles, 1, 2), 256, 61440>>>(
            pXshi, pXslo, pWhi + WOFF_ATT(i, 0), pWlo + WOFF_ATT(i, 0),
            attb + (size_t)i * KKk * ATTD, attq + (size_t)i * KKk * ATTD,
            pSim, NN);
        k_combine<<<(NN + 7) / 8, 256>>>();
    }

    hmma_gemm<128, 128, 256, 1, 1><<<dim3(nTiles, 1), 256, 81920>>>(
        pHhi, pHlo, pWhi + WOFF_P1, pWlo + WOFF_P1, pb1, nullptr, pT1hi, pT1lo, NN);
    hmma_gemm<64, 64, 128, 1, 0><<<dim3(nTiles, 1), 256, 61440>>>(
        pT1hi, pT1lo, pWhi + WOFF_P2, pWlo + WOFF_P2, pb2, (float*)d_out,
        nullptr, nullptr, NN);
}

// round 14
// speedup vs baseline: 1.0998x; 1.0998x over previous
#include <cuda_runtime.h>
#include <cuda_bf16.h>
#include <cstdint>

#define NN 100000
#define EE 400000
#define KKk 2
#define DD 256
#define ATTD 64
#define LLn 3
#define HH1 128
#define HH2 64
#define KN (KKk*NN)
#define KE (KKk*EE)
#define EPSF 1e-5f
#define SLOPE 0.01f
#define NB_SCAN ((KN + 1023) / 1024)

// ----------------------------------------------------------------------------
// Scratch (static device globals)
// ----------------------------------------------------------------------------
__device__ __nv_bfloat16 g_hhi[(size_t)NN * DD];
__device__ __nv_bfloat16 g_hlo[(size_t)NN * DD];
__device__ __nv_bfloat16 g_xwhi[(size_t)NN * DD];
__device__ __nv_bfloat16 g_xwlo[(size_t)NN * DD];
__device__ __nv_bfloat16 g_xshi[(size_t)KKk * NN * DD];
__device__ __nv_bfloat16 g_xslo[(size_t)KKk * NN * DD];
__device__ __nv_bfloat16 g_t1hi[(size_t)NN * HH1];
__device__ __nv_bfloat16 g_t1lo[(size_t)NN * HH1];
__device__ float g_sim[KN];
__device__ float g_sum[DD];
__device__ float g_sq[DD];
__device__ float g_scale[DD];
__device__ float g_shift[DD];
__device__ float g_deg[KN];
__device__ float g_dinv[KN];
__device__ int   g_cnt[KN];
__device__ int   g_ptr[KN];
__device__ int   g_fill[KN];
__device__ int   g_scn[KN];
__device__ int   g_bsum[256];
__device__ int   g_rowS[KE];
__device__ float g_normS[KE];

// Transposed + bf16-split weights, [n][k] layout.
#define WOFF_GCN(i)    ((size_t)(i) * 65536)
#define WOFF_ATT(i, k) (196608u + (size_t)((i) * 2 + (k)) * 16384)
#define WOFF_P1        294912u
#define WOFF_P2        327680u
#define WT_TOT 335872
__device__ __nv_bfloat16 g_whi[WT_TOT];
__device__ __nv_bfloat16 g_wlo[WT_TOT];

// ----------------------------------------------------------------------------
// PTX helpers
// ----------------------------------------------------------------------------
__device__ __forceinline__ uint32_t smem_u32(const void* p) {
    uint32_t a;
    asm("{ .reg .u64 t; cvta.to.shared.u64 t, %1; cvt.u32.u64 %0, t; }"
        : "=r"(a) : "l"(p));
    return a;
}
__device__ __forceinline__ void ldsm4(uint32_t* r, uint32_t addr) {
    asm volatile("ldmatrix.sync.aligned.m8n8.x4.shared.b16 {%0,%1,%2,%3},[%4];"
                 : "=r"(r[0]), "=r"(r[1]), "=r"(r[2]), "=r"(r[3]) : "r"(addr));
}
__device__ __forceinline__ void mma16816(float* c, const uint32_t* a, const uint32_t* b) {
    asm volatile(
        "mma.sync.aligned.m16n8k16.row.col.f32.bf16.bf16.f32 "
        "{%0,%1,%2,%3},{%4,%5,%6,%7},{%8,%9},{%0,%1,%2,%3};"
        : "+f"(c[0]), "+f"(c[1]), "+f"(c[2]), "+f"(c[3])
        : "r"(a[0]), "r"(a[1]), "r"(a[2]), "r"(a[3]), "r"(b[0]), "r"(b[1]));
}
__device__ __forceinline__ void cpa16(uint32_t dst, const void* src) {
    asm volatile("cp.async.cg.shared.global [%0], [%1], 16;" :: "r"(dst), "l"(src));
}
__device__ __forceinline__ void cpa_commit() {
    asm volatile("cp.async.commit_group;" ::: "memory");
}
template <int Nw>
__device__ __forceinline__ void cpa_wait() {
    asm volatile("cp.async.wait_group %0;" :: "n"(Nw) : "memory");
}
__device__ __forceinline__ void split_bf16(float v, __nv_bfloat16& h, __nv_bfloat16& l) {
    h = __float2bfloat16(v);
    l = __float2bfloat16(v - __bfloat162float(h));
}
// L2 policies (createpolicy; any-width via cache_hint on BOTH ld and st)
__device__ __forceinline__ uint64_t pol_evl() {
    uint64_t p;
    asm("createpolicy.fractional.L2::evict_last.b64 %0, 1.0;" : "=l"(p));
    return p;
}
__device__ __forceinline__ uint64_t pol_evf() {
    uint64_t p;
    asm("createpolicy.fractional.L2::evict_first.b64 %0, 1.0;" : "=l"(p));
    return p;
}
__device__ __forceinline__ uint4 ldg_pol128(const void* p, uint64_t pol) {
    uint4 v;
    asm volatile("ld.global.L2::cache_hint.v4.u32 {%0,%1,%2,%3}, [%4], %5;"
                 : "=r"(v.x), "=r"(v.y), "=r"(v.z), "=r"(v.w)
                 : "l"(p), "l"(pol));
    return v;
}
__device__ __forceinline__ void stg_pol128(void* p, uint4 v, uint64_t pol) {
    asm volatile("st.global.L2::cache_hint.v4.u32 [%0], {%1,%2,%3,%4}, %5;"
                 :: "l"(p), "r"(v.x), "r"(v.y), "r"(v.z), "r"(v.w), "l"(pol)
                 : "memory");
}
__device__ __forceinline__ void stg_pol64(void* p, uint2 v, uint64_t pol) {
    asm volatile("st.global.L2::cache_hint.v2.u32 [%0], {%1,%2}, %3;"
                 :: "l"(p), "r"(v.x), "r"(v.y), "l"(pol) : "memory");
}
__device__ __forceinline__ void stg_pol32(void* p, uint32_t v, uint64_t pol) {
    asm volatile("st.global.L2::cache_hint.u32 [%0], %1, %2;"
                 :: "l"(p), "r"(v), "l"(pol) : "memory");
}

// ----------------------------------------------------------------------------
// Fused zero kernel
// ----------------------------------------------------------------------------
__global__ void k_zero_all() {
    int i = blockIdx.x * blockDim.x + threadIdx.x;
    if (i < KN) { g_deg[i] = 0.f; g_cnt[i] = 0; g_fill[i] = 0; }
    if (i < DD) { g_sum[i] = 0.f; g_sq[i] = 0.f; }
}

// ----------------------------------------------------------------------------
// Fused weight transpose + bf16 split
// ----------------------------------------------------------------------------
__global__ void k_wsplit_all(const float* __restrict__ gcnW,
                             const float* __restrict__ attW,
                             const float* __restrict__ pW1,
                             const float* __restrict__ pW2) {
    int i = blockIdx.x * blockDim.x + threadIdx.x;
    if (i >= WT_TOT) return;
    const float* src;
    int rem, Kd, Nd, base;
    if (i < 196608) {
        int m = i >> 16; rem = i & 65535;
        src = gcnW + (size_t)m * 65536; Kd = 256; Nd = 256; base = m * 65536;
    } else if (i < 294912) {
        int j = (i - 196608) >> 14; rem = (i - 196608) & 16383;
        src = attW + (size_t)j * 16384; Kd = 256; Nd = 64; base = 196608 + j * 16384;
    } else if (i < 327680) {
        rem = i - 294912; src = pW1; Kd = 256; Nd = 128; base = 294912;
    } else {
        rem = i - 327680; src = pW2; Kd = 128; Nd = 64; base = 327680;
    }
    int k = rem / Nd, n = rem - k * Nd;
    float v = src[rem];
    __nv_bfloat16 h, l;
    split_bf16(v, h, l);
    g_whi[base + n * Kd + k] = h;
    g_wlo[base + n * Kd + k] = l;
}

// ----------------------------------------------------------------------------
// BatchNorm: colstats -> fin (scale/shift) -> bn (2 vector loads/thread)
// ----------------------------------------------------------------------------
__global__ void k_colstats(const float* __restrict__ x) {
    int d = threadIdx.x;
    float s = 0.f, q = 0.f;
    for (int r = blockIdx.x; r < NN; r += gridDim.x) {
        float v = x[(size_t)r * DD + d];
        s += v;
        q += v * v;
    }
    atomicAdd(&g_sum[d], s);
    atomicAdd(&g_sq[d], q);
}
__global__ void k_fin(const float* __restrict__ gamma, const float* __restrict__ beta) {
    int d = threadIdx.x;
    float mu  = g_sum[d] * (1.f / NN);
    float var = g_sq[d] * (1.f / NN) - mu * mu;
    float istd = rsqrtf(var + EPSF);
    float sc = istd * gamma[d];
    g_scale[d] = sc;
    g_shift[d] = beta[d] - mu * sc;
}
__global__ void k_bn(const float* __restrict__ x) {
    int i = blockIdx.x * blockDim.x + threadIdx.x;
    if (i >= NN * DD / 4) return;
    uint64_t pl = pol_evl();
    int d = (i & 63) * 4;
    float4 v = ((const float4*)x)[i];
    float4 sc = *(const float4*)(g_scale + d);
    float4 sh = *(const float4*)(g_shift + d);
    float f[4];
    f[0] = v.x * sc.x + sh.x;
    f[1] = v.y * sc.y + sh.y;
    f[2] = v.z * sc.z + sh.z;
    f[3] = v.w * sc.w + sh.w;
    __nv_bfloat16 h[4], l[4];
#pragma unroll
    for (int j = 0; j < 4; j++) split_bf16(f[j], h[j], l[j]);
    stg_pol64(g_hhi + (size_t)i * 4, *(uint2*)h, pl);
    stg_pol64(g_hlo + (size_t)i * 4, *(uint2*)l, pl);
}

// ----------------------------------------------------------------------------
// CSR build
// ----------------------------------------------------------------------------
__global__ void k_degcnt(const int* __restrict__ ei, const float* __restrict__ ew) {
    int i = blockIdx.x * blockDim.x + threadIdx.x;
    if (i >= KE) return;
    int k = i / EE, e = i - k * EE;
    int col = ei[(size_t)k * 2 * EE + EE + e];
    float w = ew[i];
    atomicAdd(&g_deg[k * NN + col], w);
    atomicAdd(&g_cnt[k * NN + col], 1);
}
__global__ void k_scan1() {
    __shared__ int s[1024];
    int t = threadIdx.x;
    int i = blockIdx.x * 1024 + t;
    if (i < KN) {
        float d = g_deg[i];
        g_dinv[i] = d > 0.f ? rsqrtf(d) : 0.f;
    }
    s[t] = (i < KN) ? g_cnt[i] : 0;
    __syncthreads();
    for (int off = 1; off < 1024; off <<= 1) {
        int u = (t >= off) ? s[t - off] : 0;
        __syncthreads();
        s[t] += u;
        __syncthreads();
    }
    if (i < KN) g_scn[i] = s[t];
    if (t == 1023) g_bsum[blockIdx.x] = s[1023];
}
__global__ void k_scan3(int nb) {
    __shared__ int sb[256];
    __shared__ int sOff;
    int t = threadIdx.x;
    if (t < nb) sb[t] = g_bsum[t];
    __syncthreads();
    if (t == 0) {
        int run = 0;
        for (int b = 0; b < (int)blockIdx.x; b++) run += sb[b];
        sOff = run;
    }
    __syncthreads();
    int i = blockIdx.x * 1024 + t;
    if (i >= KN) return;
    g_ptr[i] = g_scn[i] - g_cnt[i] + sOff;
}
__global__ void k_scatter(const int* __restrict__ ei, const float* __restrict__ ew) {
    int i = blockIdx.x * blockDim.x + threadIdx.x;
    if (i >= KE) return;
    int k = i / EE, e = i - k * EE;
    int row = ei[(size_t)k * 2 * EE + e];
    int col = ei[(size_t)k * 2 * EE + EE + e];
    float w = ew[i];
    int b = k * NN + col;
    int p = g_ptr[b] + atomicAdd(&g_fill[b], 1);
    g_rowS[p]  = row;
    g_normS[p] = g_dinv[b] * w * g_dinv[k * NN + row];
}

// ----------------------------------------------------------------------------
// Gather aggregation: one warp per (k,node), 4-edge unrolled (MLP ~16).
// ----------------------------------------------------------------------------
__global__ void k_aggregate(const float* __restrict__ bias) {
    int node = (blockIdx.x * blockDim.x + threadIdx.x) >> 5;
    int lane = threadIdx.x & 31;
    if (node >= KN) return;
    uint64_t pf = pol_evf();
    uint64_t pl = pol_evl();
    int s = g_ptr[node], c = g_cnt[node];
    float a[8];
#pragma unroll
    for (int j = 0; j < 8; j++) a[j] = 0.f;
    int co = lane * 8;
    int e = 0;
    for (; e + 4 <= c; e += 4) {
        int r0 = g_rowS[s + e],     r1 = g_rowS[s + e + 1];
        int r2 = g_rowS[s + e + 2], r3 = g_rowS[s + e + 3];
        float nv0 = g_normS[s + e],     nv1 = g_normS[s + e + 1];
        float nv2 = g_normS[s + e + 2], nv3 = g_normS[s + e + 3];
        uint4 h0 = ldg_pol128(g_xwhi + (size_t)r0 * DD + co, pl);
        uint4 l0 = ldg_pol128(g_xwlo + (size_t)r0 * DD + co, pl);
        uint4 h1 = ldg_pol128(g_xwhi + (size_t)r1 * DD + co, pl);
        uint4 l1 = ldg_pol128(g_xwlo + (size_t)r1 * DD + co, pl);
        uint4 h2 = ldg_pol128(g_xwhi + (size_t)r2 * DD + co, pl);
        uint4 l2 = ldg_pol128(g_xwlo + (size_t)r2 * DD + co, pl);
        uint4 h3 = ldg_pol128(g_xwhi + (size_t)r3 * DD + co, pl);
        uint4 l3 = ldg_pol128(g_xwlo + (size_t)r3 * DD + co, pl);
        const __nv_bfloat16* hp0 = (const __nv_bfloat16*)&h0;
        const __nv_bfloat16* lp0 = (const __nv_bfloat16*)&l0;
        const __nv_bfloat16* hp1 = (const __nv_bfloat16*)&h1;
        const __nv_bfloat16* lp1 = (const __nv_bfloat16*)&l1;
        const __nv_bfloat16* hp2 = (const __nv_bfloat16*)&h2;
        const __nv_bfloat16* lp2 = (const __nv_bfloat16*)&l2;
        const __nv_bfloat16* hp3 = (const __nv_bfloat16*)&h3;
        const __nv_bfloat16* lp3 = (const __nv_bfloat16*)&l3;
#pragma unroll
        for (int j = 0; j < 8; j++) {
            a[j] += nv0 * (__bfloat162float(hp0[j]) + __bfloat162float(lp0[j]));
            a[j] += nv1 * (__bfloat162float(hp1[j]) + __bfloat162float(lp1[j]));
            a[j] += nv2 * (__bfloat162float(hp2[j]) + __bfloat162float(lp2[j]));
            a[j] += nv3 * (__bfloat162float(hp3[j]) + __bfloat162float(lp3[j]));
        }
    }
    for (; e < c; e++) {
        int r = g_rowS[s + e];
        float nv = g_normS[s + e];
        uint4 hv = ldg_pol128(g_xwhi + (size_t)r * DD + co, pl);
        uint4 lv = ldg_pol128(g_xwlo + (size_t)r * DD + co, pl);
        const __nv_bfloat16* hp = (const __nv_bfloat16*)&hv;
        const __nv_bfloat16* lp = (const __nv_bfloat16*)&lv;
#pragma unroll
        for (int j = 0; j < 8; j++)
            a[j] += nv * (__bfloat162float(hp[j]) + __bfloat162float(lp[j]));
    }
    float4 b0 = *(const float4*)(bias + co);
    float4 b1 = *(const float4*)(bias + co + 4);
    a[0] += b0.x; a[1] += b0.y; a[2] += b0.z; a[3] += b0.w;
    a[4] += b1.x; a[5] += b1.y; a[6] += b1.z; a[7] += b1.w;
    __nv_bfloat16 ho[8], lo[8];
#pragma unroll
    for (int j = 0; j < 8; j++) split_bf16(a[j], ho[j], lo[j]);
    stg_pol128(g_xshi + (size_t)node * DD + co, *(uint4*)ho, pf);
    stg_pol128(g_xslo + (size_t)node * DD + co, *(uint4*)lo, pf);
}

// ----------------------------------------------------------------------------
// HMMA split-bf16 GEMM, cp.async double-buffered
// ----------------------------------------------------------------------------
template <int BN_, int NOUT, int KDIM, int ACT, int OSPLIT>
__global__ void __launch_bounds__(256, 2) hmma_gemm(
    const __nv_bfloat16* __restrict__ Ahi, const __nv_bfloat16* __restrict__ Alo,
    const __nv_bfloat16* __restrict__ Bhi, const __nv_bfloat16* __restrict__ Blo,
    const float* __restrict__ bias, float* __restrict__ C,
    __nv_bfloat16* __restrict__ Chi, __nv_bfloat16* __restrict__ Clo, int M)
{
    constexpr int LDA = 40;
    constexpr int WN = BN_ / 2;
    constexpr int NT = WN / 8;
    constexpr int NC = KDIM / 32;
    constexpr int ABYTES = 128 * LDA * 2;
    constexpr int BOFF   = 2 * ABYTES;
    constexpr int BBYTES = BN_ * LDA * 2;
    constexpr int SSTAGE = BOFF + 2 * BBYTES;
    extern __shared__ char dynsm[];
    uint32_t smBase = smem_u32(dynsm);

    int tid = threadIdx.x, wid = tid >> 5, lane = tid & 31;
    int warpM = wid & 3, warpN = wid >> 2;
    int row0 = blockIdx.x * 128;
    int colBase = blockIdx.y * BN_;

    float acc[2][NT][4];
#pragma unroll
    for (int mt = 0; mt < 2; mt++)
#pragma unroll
        for (int nt = 0; nt < NT; nt++)
#pragma unroll
            for (int q = 0; q < 4; q++) acc[mt][nt][q] = 0.f;

    auto load_stage = [&](int kc, uint32_t sb) {
        constexpr int TOT = 1024 + 8 * BN_;
#pragma unroll
        for (int c = tid; c < TOT; c += 256) {
            const __nv_bfloat16* src;
            uint32_t dst;
            if (c < 1024) {
                int mat = c >> 9;
                int cc = c & 511;
                int r = cc >> 2, col = (cc & 3) << 3;
                int gr = row0 + r;
                gr = gr < M ? gr : (M - 1);
                src = (mat ? Alo : Ahi) + (size_t)gr * KDIM + kc * 32 + col;
                dst = sb + mat * ABYTES + (uint32_t)(r * LDA + col) * 2;
            } else {
                int c2 = c - 1024;
                int mat = c2 / (BN_ * 4);
                int cc = c2 % (BN_ * 4);
                int r = cc >> 2, col = (cc & 3) << 3;
                src = (mat ? Blo : Bhi) + (size_t)(colBase + r) * KDIM + kc * 32 + col;
                dst = sb + BOFF + mat * BBYTES + (uint32_t)(r * LDA + col) * 2;
            }
            cpa16(dst, src);
        }
        cpa_commit();
    };

    load_stage(0, smBase);
    for (int kc = 0; kc < NC; kc++) {
        if (kc + 1 < NC) {
            load_stage(kc + 1, smBase + (uint32_t)((kc + 1) & 1) * SSTAGE);
            cpa_wait<1>();
        } else {
            cpa_wait<0>();
        }
        __syncthreads();
        uint32_t st = smBase + (uint32_t)(kc & 1) * SSTAGE;
        uint32_t uAhi = st, uAlo = st + ABYTES;
        uint32_t uBhi = st + BOFF, uBlo = st + BOFF + BBYTES;

#pragma unroll
        for (int ks = 0; ks < 2; ks++) {
            uint32_t ahi[2][4], alo[2][4];
#pragma unroll
            for (int mt = 0; mt < 2; mt++) {
                uint32_t aoff =
                    ((warpM * 32 + mt * 16 + (lane & 15)) * LDA + (lane >> 4) * 8 + ks * 16) * 2;
                ldsm4(ahi[mt], uAhi + aoff);
                ldsm4(alo[mt], uAlo + aoff);
            }
            uint32_t bhi[NT][2], blo[NT][2];
#pragma unroll
            for (int p = 0; p < NT / 2; p++) {
                int nrow = warpN * WN + p * 16 + (lane & 7) + ((lane & 16) >> 1);
                int kcol = ks * 16 + (lane & 8);
                uint32_t boff = (uint32_t)(nrow * LDA + kcol) * 2;
                uint32_t t[4];
                ldsm4(t, uBhi + boff);
                bhi[2 * p][0] = t[0]; bhi[2 * p][1] = t[1];
                bhi[2 * p + 1][0] = t[2]; bhi[2 * p + 1][1] = t[3];
                ldsm4(t, uBlo + boff);
                blo[2 * p][0] = t[0]; blo[2 * p][1] = t[1];
                blo[2 * p + 1][0] = t[2]; blo[2 * p + 1][1] = t[3];
            }
#pragma unroll
            for (int mt = 0; mt < 2; mt++)
#pragma unroll
                for (int nt = 0; nt < NT; nt++) {
                    mma16816(acc[mt][nt], ahi[mt], bhi[nt]);
                    mma16816(acc[mt][nt], ahi[mt], blo[nt]);
                    mma16816(acc[mt][nt], alo[mt], bhi[nt]);
                }
        }
        __syncthreads();
    }

    uint64_t pl = pol_evl();
#pragma unroll
    for (int mt = 0; mt < 2; mt++) {
        int row = row0 + warpM * 32 + mt * 16 + (lane >> 2);
#pragma unroll
        for (int nt = 0; nt < NT; nt++) {
            int col = colBase + warpN * WN + nt * 8 + (lane & 3) * 2;
            float b0 = 0.f, b1 = 0.f;
            if (bias) { b0 = bias[col]; b1 = bias[col + 1]; }
            float v0 = acc[mt][nt][0] + b0, v1 = acc[mt][nt][1] + b1;
            float v2 = acc[mt][nt][2] + b0, v3 = acc[mt][nt][3] + b1;
            if (ACT == 1) {
                v0 = v0 > 0.f ? v0 : SLOPE * v0; v1 = v1 > 0.f ? v1 : SLOPE * v1;
                v2 = v2 > 0.f ? v2 : SLOPE * v2; v3 = v3 > 0.f ? v3 : SLOPE * v3;
            }
            if (OSPLIT) {
                __nv_bfloat16 h0, l0, h1, l1;
                if (row < M) {
                    split_bf16(v0, h0, l0); split_bf16(v1, h1, l1);
                    __nv_bfloat16 hp[2] = {h0, h1}, lp[2] = {l0, l1};
                    stg_pol32(Chi + (size_t)row * NOUT + col, *(uint32_t*)hp, pl);
                    stg_pol32(Clo + (size_t)row * NOUT + col, *(uint32_t*)lp, pl);
                }
                if (row + 8 < M) {
                    split_bf16(v2, h0, l0); split_bf16(v3, h1, l1);
                    __nv_bfloat16 hp[2] = {h0, h1}, lp[2] = {l0, l1};
                    stg_pol32(Chi + (size_t)(row + 8) * NOUT + col, *(uint32_t*)hp, pl);
                    stg_pol32(Clo + (size_t)(row + 8) * NOUT + col, *(uint32_t*)lp, pl);
                }
            } else {
                if (row < M)
                    *(float2*)(C + (size_t)row * NOUT + col) = make_float2(v0, v1);
                if (row + 8 < M)
                    *(float2*)(C + (size_t)(row + 8) * NOUT + col) = make_float2(v2, v3);
            }
        }
    }
}

// ----------------------------------------------------------------------------
// Attention GEMM with fused sim epilogue
// ----------------------------------------------------------------------------
__global__ void __launch_bounds__(256, 2) hmma_att(
    const __nv_bfloat16* __restrict__ AhiB, const __nv_bfloat16* __restrict__ AloB,
    const __nv_bfloat16* __restrict__ BhiB, const __nv_bfloat16* __restrict__ BloB,
    const float* __restrict__ biasB, const float* __restrict__ qB,
    float* __restrict__ simB, int M)
{
    constexpr int LDA = 40, NC = 8;
    constexpr int ABYTES = 128 * LDA * 2;
    constexpr int BOFF = 2 * ABYTES;
    constexpr int BBYTES = 64 * LDA * 2;
    constexpr int SSTAGE = BOFF + 2 * BBYTES;
    extern __shared__ char dynsm[];
    uint32_t smBase = smem_u32(dynsm);

    int tid = threadIdx.x, wid = tid >> 5, lane = tid & 31;
    int row0 = blockIdx.x * 128;
    int kk = blockIdx.z;
    const __nv_bfloat16* Ahi = AhiB + (size_t)kk * NN * DD;
    const __nv_bfloat16* Alo = AloB + (size_t)kk * NN * DD;
    const __nv_bfloat16* Bhi = BhiB + (size_t)kk * 16384;
    const __nv_bfloat16* Blo = BloB + (size_t)kk * 16384;
    const float* bias = biasB + kk * ATTD;
    const float* q    = qB + kk * ATTD;
    float* sim        = simB + (size_t)kk * NN;

    float acc[8][4];
#pragma unroll
    for (int nt = 0; nt < 8; nt++)
#pragma unroll
        for (int p = 0; p < 4; p++) acc[nt][p] = 0.f;

    auto load_stage = [&](int kc, uint32_t sb) {
        constexpr int TOT = 1024 + 512;
#pragma unroll
        for (int c = tid; c < TOT; c += 256) {
            const __nv_bfloat16* src;
            uint32_t dst;
            if (c < 1024) {
                int mat = c >> 9;
                int cc = c & 511;
                int r = cc >> 2, col = (cc & 3) << 3;
                int gr = row0 + r;
                gr = gr < M ? gr : (M - 1);
                src = (mat ? Alo : Ahi) + (size_t)gr * DD + kc * 32 + col;
                dst = sb + mat * ABYTES + (uint32_t)(r * LDA + col) * 2;
            } else {
                int c2 = c - 1024;
                int mat = c2 >> 8;
                int cc = c2 & 255;
                int r = cc >> 2, col = (cc & 3) << 3;
                src = (mat ? Blo : Bhi) + (size_t)r * DD + kc * 32 + col;
                dst = sb + BOFF + mat * BBYTES + (uint32_t)(r * LDA + col) * 2;
            }
            cpa16(dst, src);
        }
        cpa_commit();
    };

    load_stage(0, smBase);
    for (int kc = 0; kc < NC; kc++) {
        if (kc + 1 < NC) {
            load_stage(kc + 1, smBase + (uint32_t)((kc + 1) & 1) * SSTAGE);
            cpa_wait<1>();
        } else {
            cpa_wait<0>();
        }
        __syncthreads();
        uint32_t st = smBase + (uint32_t)(kc & 1) * SSTAGE;
        uint32_t uAhi = st, uAlo = st + ABYTES;
        uint32_t uBhi = st + BOFF, uBlo = st + BOFF + BBYTES;

#pragma unroll
        for (int ks = 0; ks < 2; ks++) {
            uint32_t ahi[4], alo[4];
            uint32_t aoff =
                ((wid * 16 + (lane & 15)) * LDA + (lane >> 4) * 8 + ks * 16) * 2;
            ldsm4(ahi, uAhi + aoff);
            ldsm4(alo, uAlo + aoff);
            uint32_t bhi[8][2], blo[8][2];
#pragma unroll
            for (int p = 0; p < 4; p++) {
                int nrow = p * 16 + (lane & 7) + ((lane & 16) >> 1);
                int kcol = ks * 16 + (lane & 8);
                uint32_t boff = (uint32_t)(nrow * LDA + kcol) * 2;
                uint32_t t[4];
                ldsm4(t, uBhi + boff);
                bhi[2 * p][0] = t[0]; bhi[2 * p][1] = t[1];
                bhi[2 * p + 1][0] = t[2]; bhi[2 * p + 1][1] = t[3];
                ldsm4(t, uBlo + boff);
                blo[2 * p][0] = t[0]; blo[2 * p][1] = t[1];
                blo[2 * p + 1][0] = t[2]; blo[2 * p + 1][1] = t[3];
            }
#pragma unroll
            for (int nt = 0; nt < 8; nt++) {
                mma16816(acc[nt], ahi, bhi[nt]);
                mma16816(acc[nt], ahi, blo[nt]);
                mma16816(acc[nt], alo, bhi[nt]);
            }
        }
        __syncthreads();
    }

    float t0 = 0.f, t1 = 0.f;
#pragma unroll
    for (int nt = 0; nt < 8; nt++) {
        int col = nt * 8 + (lane & 3) * 2;
        float b0 = bias[col], b1 = bias[col + 1];
        float q0 = q[col], q1 = q[col + 1];
        t0 += tanhf(acc[nt][0] + b0) * q0 + tanhf(acc[nt][1] + b1) * q1;
        t1 += tanhf(acc[nt][2] + b0) * q0 + tanhf(acc[nt][3] + b1) * q1;
    }
    t0 += __shfl_xor_sync(0xffffffffu, t0, 1);
    t0 += __shfl_xor_sync(0xffffffffu, t0, 2);
    t1 += __shfl_xor_sync(0xffffffffu, t1, 1);
    t1 += __shfl_xor_sync(0xffffffffu, t1, 2);
    if ((lane & 3) == 0) {
        int row = row0 + wid * 16 + (lane >> 2);
        if (row < M) sim[row] = t0;
        if (row + 8 < M) sim[row + 8] = t1;
    }
}

// ----------------------------------------------------------------------------
// Softmax over K + combine + relu
// ----------------------------------------------------------------------------
__global__ void k_combine() {
    int node = (blockIdx.x * blockDim.x + threadIdx.x) >> 5;
    int lane = threadIdx.x & 31;
    if (node >= NN) return;
    uint64_t pl = pol_evl();
    uint64_t pf = pol_evf();
    float p0 = g_sim[node], p1 = g_sim[NN + node];
    float m = fmaxf(p0, p1);
    float e0 = expf(p0 - m), e1 = expf(p1 - m);
    float inv = 1.f / (e0 + e1);
    float a0v = e0 * inv, a1v = e1 * inv;
    size_t off = (size_t)node * DD + lane * 8;
    uint4 h0 = ldg_pol128(g_xshi + off, pf);
    uint4 l0 = ldg_pol128(g_xslo + off, pf);
    uint4 h1 = ldg_pol128(g_xshi + (size_t)NN * DD + off, pf);
    uint4 l1 = ldg_pol128(g_xslo + (size_t)NN * DD + off, pf);
    const __nv_bfloat16* ph0 = (const __nv_bfloat16*)&h0;
    const __nv_bfloat16* pl0 = (const __nv_bfloat16*)&l0;
    const __nv_bfloat16* ph1 = (const __nv_bfloat16*)&h1;
    const __nv_bfloat16* pl1 = (const __nv_bfloat16*)&l1;
    __nv_bfloat16 oh[8], ol[8];
#pragma unroll
    for (int j = 0; j < 8; j++) {
        float f0 = __bfloat162float(ph0[j]) + __bfloat162float(pl0[j]);
        float f1 = __bfloat162float(ph1[j]) + __bfloat162float(pl1[j]);
        float r = fmaxf(a0v * f0 + a1v * f1, 0.f);
        split_bf16(r, oh[j], ol[j]);
    }
    stg_pol128(g_hhi + off, *(uint4*)oh, pl);
    stg_pol128(g_hlo + off, *(uint4*)ol, pl);
}

// ----------------------------------------------------------------------------
// Host orchestration
// ----------------------------------------------------------------------------
extern "C" void kernel_launch(void* const* d_in, const int* in_sizes, int n_in,
                              void* d_out, int out_size) {
    const float* x     = (const float*)d_in[0];
    const int*   ei    = (const int*)d_in[1];
    const float* ew    = (const float*)d_in[2];
    const float* gamma = (const float*)d_in[3];
    const float* beta  = (const float*)d_in[4];
    const float* gcnW  = (const float*)d_in[5];
    const float* gcnb  = (const float*)d_in[6];
    const float* attW  = (const float*)d_in[7];
    const float* attb  = (const float*)d_in[8];
    const float* attq  = (const float*)d_in[9];
    const float* pW1   = (const float*)d_in[10];
    const float* pb1   = (const float*)d_in[11];
    const float* pW2   = (const float*)d_in[12];
    const float* pb2   = (const float*)d_in[13];

    float *pSim;
    __nv_bfloat16 *pWhi, *pWlo, *pHhi, *pHlo, *pXwhi, *pXwlo, *pXshi, *pXslo,
                  *pT1hi, *pT1lo;
    cudaGetSymbolAddress((void**)&pSim, g_sim);
    cudaGetSymbolAddress((void**)&pWhi, g_whi);
    cudaGetSymbolAddress((void**)&pWlo, g_wlo);
    cudaGetSymbolAddress((void**)&pHhi, g_hhi);
    cudaGetSymbolAddress((void**)&pHlo, g_hlo);
    cudaGetSymbolAddress((void**)&pXwhi, g_xwhi);
    cudaGetSymbolAddress((void**)&pXwlo, g_xwlo);
    cudaGetSymbolAddress((void**)&pXshi, g_xshi);
    cudaGetSymbolAddress((void**)&pXslo, g_xslo);
    cudaGetSymbolAddress((void**)&pT1hi, g_t1hi);
    cudaGetSymbolAddress((void**)&pT1lo, g_t1lo);

    cudaFuncSetAttribute((const void*)hmma_gemm<128, 256, 256, 0, 1>,
                         cudaFuncAttributeMaxDynamicSharedMemorySize, 81920);
    cudaFuncSetAttribute((const void*)hmma_att,
                         cudaFuncAttributeMaxDynamicSharedMemorySize, 61440);
    cudaFuncSetAttribute((const void*)hmma_gemm<128, 128, 256, 1, 1>,
                         cudaFuncAttributeMaxDynamicSharedMemorySize, 81920);
    cudaFuncSetAttribute((const void*)hmma_gemm<64, 64, 128, 1, 0>,
                         cudaFuncAttributeMaxDynamicSharedMemorySize, 61440);

    k_zero_all<<<(KN + 255) / 256, 256>>>();
    k_wsplit_all<<<(WT_TOT + 255) / 256, 256>>>(gcnW, attW, pW1, pW2);

    k_colstats<<<512, 256>>>(x);
    k_fin<<<1, 256>>>(gamma, beta);
    k_bn<<<(NN * DD / 4 + 255) / 256, 256>>>(x);

    k_degcnt<<<(KE + 255) / 256, 256>>>(ei, ew);
    k_scan1<<<NB_SCAN, 1024>>>();
    k_scan3<<<NB_SCAN, 1024>>>(NB_SCAN);
    k_scatter<<<(KE + 255) / 256, 256>>>(ei, ew);

    int nTiles = (NN + 127) / 128;

    for (int i = 0; i < LLn; i++) {
        hmma_gemm<128, 256, 256, 0, 1><<<dim3(nTiles, 2), 256, 81920>>>(
            pHhi, pHlo, pWhi + WOFF_GCN(i), pWlo + WOFF_GCN(i),
            nullptr, nullptr, pXwhi, pXwlo, NN);
        k_aggregate<<<(KN + 7) / 8, 256>>>(gcnb + (size_t)i * DD);
        hmma_att<<<dim3(nTiles, 1, 2), 256, 61440>>>(
            pXshi, pXslo, pWhi + WOFF_ATT(i, 0), pWlo + WOFF_ATT(i, 0),
            attb + (size_t)i * KKk * ATTD, attq + (size_t)i * KKk * ATTD,
            pSim, NN);
        k_combine<<<(NN + 7) / 8, 256>>>();
    }

    hmma_gemm<128, 128, 256, 1, 1><<<dim3(nTiles, 1), 256, 81920>>>(
        pHhi, pHlo, pWhi + WOFF_P1, pWlo + WOFF_P1, pb1, nullptr, pT1hi, pT1lo, NN);
    hmma_gemm<64, 64, 128, 1, 0><<<dim3(nTiles, 1), 256, 61440>>>(
        pT1hi, pT1lo, pWhi + WOFF_P2, pWlo + WOFF_P2, pb2, (float*)d_out,
        nullptr, nullptr, NN);
}

// round 16
// speedup vs baseline: 1.2340x; 1.1220x over previous
#include <cuda_runtime.h>
#include <cuda_bf16.h>
#include <cstdint>

#define NN 100000
#define EE 400000
#define KKk 2
#define DD 256
#define ATTD 64
#define LLn 3
#define HH1 128
#define HH2 64
#define KN (KKk*NN)
#define KE (KKk*EE)
#define EPSF 1e-5f
#define SLOPE 0.01f
#define NB_SCAN ((KN + 1023) / 1024)
#define NB_ZERO ((KN + 255) / 256)
#define NB_WSPL ((WT_TOT + 255) / 256)
#define NB_CSTAT 512
#define NB_DEG ((KE + 255) / 256)
#define NB_BN ((NN * DD / 4 + 1023) / 1024)

// ----------------------------------------------------------------------------
// Scratch (static device globals)
// ----------------------------------------------------------------------------
__device__ __nv_bfloat16 g_hhi[(size_t)NN * DD];
__device__ __nv_bfloat16 g_hlo[(size_t)NN * DD];
__device__ float g_xw[(size_t)NN * DD];
__device__ __nv_bfloat16 g_xshi[(size_t)KKk * NN * DD];
__device__ __nv_bfloat16 g_xslo[(size_t)KKk * NN * DD];
__device__ __nv_bfloat16 g_t1hi[(size_t)NN * HH1];
__device__ __nv_bfloat16 g_t1lo[(size_t)NN * HH1];
__device__ float g_sim[KN];
__device__ float g_sum[DD];
__device__ float g_sq[DD];
__device__ float g_scale[DD];
__device__ float g_shift[DD];
__device__ float g_deg[KN];
__device__ float g_dinv[KN];
__device__ int   g_cnt[KN];
__device__ int   g_ptr[KN];
__device__ int   g_fill[KN];
__device__ int   g_scn[KN];
__device__ int   g_bsum[256];
__device__ int   g_rowS[KE];
__device__ float g_normS[KE];

// Transposed + bf16-split weights, [n][k] layout.
#define WOFF_GCN(i)    ((size_t)(i) * 65536)
#define WOFF_ATT(i, k) (196608u + (size_t)((i) * 2 + (k)) * 16384)
#define WOFF_P1        294912u
#define WOFF_P2        327680u
#define WT_TOT 335872
__device__ __nv_bfloat16 g_whi[WT_TOT];
__device__ __nv_bfloat16 g_wlo[WT_TOT];

// ----------------------------------------------------------------------------
// PTX helpers
// ----------------------------------------------------------------------------
__device__ __forceinline__ uint32_t smem_u32(const void* p) {
    uint32_t a;
    asm("{ .reg .u64 t; cvta.to.shared.u64 t, %1; cvt.u32.u64 %0, t; }"
        : "=r"(a) : "l"(p));
    return a;
}
__device__ __forceinline__ void ldsm4(uint32_t* r, uint32_t addr) {
    asm volatile("ldmatrix.sync.aligned.m8n8.x4.shared.b16 {%0,%1,%2,%3},[%4];"
                 : "=r"(r[0]), "=r"(r[1]), "=r"(r[2]), "=r"(r[3]) : "r"(addr));
}
__device__ __forceinline__ void mma16816(float* c, const uint32_t* a, const uint32_t* b) {
    asm volatile(
        "mma.sync.aligned.m16n8k16.row.col.f32.bf16.bf16.f32 "
        "{%0,%1,%2,%3},{%4,%5,%6,%7},{%8,%9},{%0,%1,%2,%3};"
        : "+f"(c[0]), "+f"(c[1]), "+f"(c[2]), "+f"(c[3])
        : "r"(a[0]), "r"(a[1]), "r"(a[2]), "r"(a[3]), "r"(b[0]), "r"(b[1]));
}
__device__ __forceinline__ void cpa16(uint32_t dst, const void* src) {
    asm volatile("cp.async.cg.shared.global [%0], [%1], 16;" :: "r"(dst), "l"(src));
}
__device__ __forceinline__ void cpa_commit() {
    asm volatile("cp.async.commit_group;" ::: "memory");
}
template <int Nw>
__device__ __forceinline__ void cpa_wait() {
    asm volatile("cp.async.wait_group %0;" :: "n"(Nw) : "memory");
}
__device__ __forceinline__ void split_bf16(float v, __nv_bfloat16& h, __nv_bfloat16& l) {
    h = __float2bfloat16(v);
    l = __float2bfloat16(v - __bfloat162float(h));
}
// L2 policies
__device__ __forceinline__ uint64_t pol_evl() {
    uint64_t p;
    asm("createpolicy.fractional.L2::evict_last.b64 %0, 1.0;" : "=l"(p));
    return p;
}
__device__ __forceinline__ uint64_t pol_evf() {
    uint64_t p;
    asm("createpolicy.fractional.L2::evict_first.b64 %0, 1.0;" : "=l"(p));
    return p;
}
__device__ __forceinline__ uint4 ldg_pol128(const void* p, uint64_t pol) {
    uint4 v;
    asm volatile("ld.global.L2::cache_hint.v4.u32 {%0,%1,%2,%3}, [%4], %5;"
                 : "=r"(v.x), "=r"(v.y), "=r"(v.z), "=r"(v.w)
                 : "l"(p), "l"(pol));
    return v;
}
__device__ __forceinline__ float4 ldg_polf4(const void* p, uint64_t pol) {
    float4 v;
    asm volatile("ld.global.L2::cache_hint.v4.f32 {%0,%1,%2,%3}, [%4], %5;"
                 : "=f"(v.x), "=f"(v.y), "=f"(v.z), "=f"(v.w)
                 : "l"(p), "l"(pol));
    return v;
}
__device__ __forceinline__ void stg_pol128(void* p, uint4 v, uint64_t pol) {
    asm volatile("st.global.L2::cache_hint.v4.u32 [%0], {%1,%2,%3,%4}, %5;"
                 :: "l"(p), "r"(v.x), "r"(v.y), "r"(v.z), "r"(v.w), "l"(pol)
                 : "memory");
}
__device__ __forceinline__ void stg_pol64(void* p, uint2 v, uint64_t pol) {
    asm volatile("st.global.L2::cache_hint.v2.u32 [%0], {%1,%2}, %3;"
                 :: "l"(p), "r"(v.x), "r"(v.y), "l"(pol) : "memory");
}
__device__ __forceinline__ void stg_pol32(void* p, uint32_t v, uint64_t pol) {
    asm volatile("st.global.L2::cache_hint.u32 [%0], %1, %2;"
                 :: "l"(p), "r"(v), "l"(pol) : "memory");
}

// ----------------------------------------------------------------------------
// Fused prologue 0: zero accumulators + weight transpose/split
// ----------------------------------------------------------------------------
__global__ void k_pro0(const float* __restrict__ gcnW, const float* __restrict__ attW,
                       const float* __restrict__ pW1, const float* __restrict__ pW2) {
    int bid = blockIdx.x;
    if (bid < NB_ZERO) {
        int i = bid * 256 + threadIdx.x;
        if (i < KN) { g_deg[i] = 0.f; g_cnt[i] = 0; g_fill[i] = 0; }
        if (i < DD) { g_sum[i] = 0.f; g_sq[i] = 0.f; }
        return;
    }
    int i = (bid - NB_ZERO) * 256 + threadIdx.x;
    if (i >= WT_TOT) return;
    const float* src;
    int rem, Kd, Nd, base;
    if (i < 196608) {
        int m = i >> 16; rem = i & 65535;
        src = gcnW + (size_t)m * 65536; Kd = 256; Nd = 256; base = m * 65536;
    } else if (i < 294912) {
        int j = (i - 196608) >> 14; rem = (i - 196608) & 16383;
        src = attW + (size_t)j * 16384; Kd = 256; Nd = 64; base = 196608 + j * 16384;
    } else if (i < 327680) {
        rem = i - 294912; src = pW1; Kd = 256; Nd = 128; base = 294912;
    } else {
        rem = i - 327680; src = pW2; Kd = 128; Nd = 64; base = 327680;
    }
    int k = rem / Nd, n = rem - k * Nd;
    float v = src[rem];
    __nv_bfloat16 h, l;
    split_bf16(v, h, l);
    g_whi[base + n * Kd + k] = h;
    g_wlo[base + n * Kd + k] = l;
}

// ----------------------------------------------------------------------------
// Fused prologue 1: BN column stats + edge degree counting
// ----------------------------------------------------------------------------
__global__ void k_pro1(const float* __restrict__ x, const int* __restrict__ ei,
                       const float* __restrict__ ew) {
    int bid = blockIdx.x;
    if (bid < NB_CSTAT) {
        int d = threadIdx.x;
        float s = 0.f, q = 0.f;
        for (int r = bid; r < NN; r += NB_CSTAT) {
            float v = x[(size_t)r * DD + d];
            s += v;
            q += v * v;
        }
        atomicAdd(&g_sum[d], s);
        atomicAdd(&g_sq[d], q);
        return;
    }
    int i = (bid - NB_CSTAT) * 256 + threadIdx.x;
    if (i >= KE) return;
    int k = i / EE, e = i - k * EE;
    int col = ei[(size_t)k * 2 * EE + EE + e];
    float w = ew[i];
    atomicAdd(&g_deg[k * NN + col], w);
    atomicAdd(&g_cnt[k * NN + col], 1);
}

// ----------------------------------------------------------------------------
// Fused prologue 2: scan1 (+dinv) | fin (extra block)
// ----------------------------------------------------------------------------
__global__ void k_pro2(const float* __restrict__ gamma, const float* __restrict__ beta) {
    int bid = blockIdx.x;
    int t = threadIdx.x;
    if (bid == NB_SCAN) {
        if (t < DD) {
            float mu  = g_sum[t] * (1.f / NN);
            float var = g_sq[t] * (1.f / NN) - mu * mu;
            float istd = rsqrtf(var + EPSF);
            float sc = istd * gamma[t];
            g_scale[t] = sc;
            g_shift[t] = beta[t] - mu * sc;
        }
        return;
    }
    __shared__ int s[1024];
    int i = bid * 1024 + t;
    if (i < KN) {
        float d = g_deg[i];
        g_dinv[i] = d > 0.f ? rsqrtf(d) : 0.f;
    }
    s[t] = (i < KN) ? g_cnt[i] : 0;
    __syncthreads();
    for (int off = 1; off < 1024; off <<= 1) {
        int u = (t >= off) ? s[t - off] : 0;
        __syncthreads();
        s[t] += u;
        __syncthreads();
    }
    if (i < KN) g_scn[i] = s[t];
    if (t == 1023) g_bsum[bid] = s[1023];
}

// ----------------------------------------------------------------------------
// Fused prologue 3: scan3 | bn (split-h production)
// ----------------------------------------------------------------------------
__global__ void k_pro3(const float* __restrict__ x) {
    int bid = blockIdx.x;
    int t = threadIdx.x;
    if (bid < NB_SCAN) {
        __shared__ int sb[256];
        __shared__ int sOff;
        if (t < 256) sb[t] = g_bsum[t];
        __syncthreads();
        if (t == 0) {
            int run = 0;
            for (int b = 0; b < bid; b++) run += sb[b];
            sOff = run;
        }
        __syncthreads();
        int i = bid * 1024 + t;
        if (i >= KN) return;
        g_ptr[i] = g_scn[i] - g_cnt[i] + sOff;
        return;
    }
    int i = (bid - NB_SCAN) * 1024 + t;
    if (i >= NN * DD / 4) return;
    uint64_t pl = pol_evl();
    int d = (i & 63) * 4;
    float4 v = ((const float4*)x)[i];
    float4 sc = *(const float4*)(g_scale + d);
    float4 sh = *(const float4*)(g_shift + d);
    float f[4];
    f[0] = v.x * sc.x + sh.x;
    f[1] = v.y * sc.y + sh.y;
    f[2] = v.z * sc.z + sh.z;
    f[3] = v.w * sc.w + sh.w;
    __nv_bfloat16 h[4], l[4];
#pragma unroll
    for (int j = 0; j < 4; j++) split_bf16(f[j], h[j], l[j]);
    stg_pol64(g_hhi + (size_t)i * 4, *(uint2*)h, pl);
    stg_pol64(g_hlo + (size_t)i * 4, *(uint2*)l, pl);
}

__global__ void k_scatter(const int* __restrict__ ei, const float* __restrict__ ew) {
    int i = blockIdx.x * blockDim.x + threadIdx.x;
    if (i >= KE) return;
    int k = i / EE, e = i - k * EE;
    int row = ei[(size_t)k * 2 * EE + e];
    int col = ei[(size_t)k * 2 * EE + EE + e];
    float w = ew[i];
    int b = k * NN + col;
    int p = g_ptr[b] + atomicAdd(&g_fill[b], 1);
    g_rowS[p]  = row;
    g_normS[p] = g_dinv[b] * w * g_dinv[k * NN + row];
}

// ----------------------------------------------------------------------------
// Gather aggregation: one warp per (k,node), 4-edge unrolled, fp32 xw.
// 8 FMA/edge (no bf16 cvts). Writes xs split bf16.
// ----------------------------------------------------------------------------
__global__ void k_aggregate(const float* __restrict__ bias) {
    int node = (blockIdx.x * blockDim.x + threadIdx.x) >> 5;
    int lane = threadIdx.x & 31;
    if (node >= KN) return;
    uint64_t pf = pol_evf();
    uint64_t pl = pol_evl();
    int s = g_ptr[node], c = g_cnt[node];
    float a[8];
#pragma unroll
    for (int j = 0; j < 8; j++) a[j] = 0.f;
    int co = lane * 8;
    int e = 0;
    for (; e + 4 <= c; e += 4) {
        int r0 = g_rowS[s + e],     r1 = g_rowS[s + e + 1];
        int r2 = g_rowS[s + e + 2], r3 = g_rowS[s + e + 3];
        float nv0 = g_normS[s + e],     nv1 = g_normS[s + e + 1];
        float nv2 = g_normS[s + e + 2], nv3 = g_normS[s + e + 3];
        float4 a0 = ldg_polf4(g_xw + (size_t)r0 * DD + co, pl);
        float4 b0 = ldg_polf4(g_xw + (size_t)r0 * DD + co + 4, pl);
        float4 a1 = ldg_polf4(g_xw + (size_t)r1 * DD + co, pl);
        float4 b1 = ldg_polf4(g_xw + (size_t)r1 * DD + co + 4, pl);
        float4 a2 = ldg_polf4(g_xw + (size_t)r2 * DD + co, pl);
        float4 b2 = ldg_polf4(g_xw + (size_t)r2 * DD + co + 4, pl);
        float4 a3 = ldg_polf4(g_xw + (size_t)r3 * DD + co, pl);
        float4 b3 = ldg_polf4(g_xw + (size_t)r3 * DD + co + 4, pl);
        a[0] += nv0 * a0.x + nv1 * a1.x + nv2 * a2.x + nv3 * a3.x;
        a[1] += nv0 * a0.y + nv1 * a1.y + nv2 * a2.y + nv3 * a3.y;
        a[2] += nv0 * a0.z + nv1 * a1.z + nv2 * a2.z + nv3 * a3.z;
        a[3] += nv0 * a0.w + nv1 * a1.w + nv2 * a2.w + nv3 * a3.w;
        a[4] += nv0 * b0.x + nv1 * b1.x + nv2 * b2.x + nv3 * b3.x;
        a[5] += nv0 * b0.y + nv1 * b1.y + nv2 * b2.y + nv3 * b3.y;
        a[6] += nv0 * b0.z + nv1 * b1.z + nv2 * b2.z + nv3 * b3.z;
        a[7] += nv0 * b0.w + nv1 * b1.w + nv2 * b2.w + nv3 * b3.w;
    }
    for (; e < c; e++) {
        int r = g_rowS[s + e];
        float nv = g_normS[s + e];
        float4 av = ldg_polf4(g_xw + (size_t)r * DD + co, pl);
        float4 bv = ldg_polf4(g_xw + (size_t)r * DD + co + 4, pl);
        a[0] += nv * av.x; a[1] += nv * av.y; a[2] += nv * av.z; a[3] += nv * av.w;
        a[4] += nv * bv.x; a[5] += nv * bv.y; a[6] += nv * bv.z; a[7] += nv * bv.w;
    }
    float4 b0 = *(const float4*)(bias + co);
    float4 b1 = *(const float4*)(bias + co + 4);
    a[0] += b0.x; a[1] += b0.y; a[2] += b0.z; a[3] += b0.w;
    a[4] += b1.x; a[5] += b1.y; a[6] += b1.z; a[7] += b1.w;
    __nv_bfloat16 ho[8], lo[8];
#pragma unroll
    for (int j = 0; j < 8; j++) split_bf16(a[j], ho[j], lo[j]);
    stg_pol128(g_xshi + (size_t)node * DD + co, *(uint4*)ho, pf);
    stg_pol128(g_xslo + (size_t)node * DD + co, *(uint4*)lo, pf);
}

// ----------------------------------------------------------------------------
// HMMA split-bf16 GEMM, cp.async double-buffered
// OSPLIT: 1 -> split bf16 out; 0 -> fp32 out
// ----------------------------------------------------------------------------
template <int BN_, int NOUT, int KDIM, int ACT, int OSPLIT>
__global__ void __launch_bounds__(256, 2) hmma_gemm(
    const __nv_bfloat16* __restrict__ Ahi, const __nv_bfloat16* __restrict__ Alo,
    const __nv_bfloat16* __restrict__ Bhi, const __nv_bfloat16* __restrict__ Blo,
    const float* __restrict__ bias, float* __restrict__ C,
    __nv_bfloat16* __restrict__ Chi, __nv_bfloat16* __restrict__ Clo, int M)
{
    constexpr int LDA = 40;
    constexpr int WN = BN_ / 2;
    constexpr int NT = WN / 8;
    constexpr int NC = KDIM / 32;
    constexpr int ABYTES = 128 * LDA * 2;
    constexpr int BOFF   = 2 * ABYTES;
    constexpr int BBYTES = BN_ * LDA * 2;
    constexpr int SSTAGE = BOFF + 2 * BBYTES;
    extern __shared__ char dynsm[];
    uint32_t smBase = smem_u32(dynsm);

    int tid = threadIdx.x, wid = tid >> 5, lane = tid & 31;
    int warpM = wid & 3, warpN = wid >> 2;
    int row0 = blockIdx.x * 128;
    int colBase = blockIdx.y * BN_;

    float acc[2][NT][4];
#pragma unroll
    for (int mt = 0; mt < 2; mt++)
#pragma unroll
        for (int nt = 0; nt < NT; nt++)
#pragma unroll
            for (int q = 0; q < 4; q++) acc[mt][nt][q] = 0.f;

    auto load_stage = [&](int kc, uint32_t sb) {
        constexpr int TOT = 1024 + 8 * BN_;
#pragma unroll
        for (int c = tid; c < TOT; c += 256) {
            const __nv_bfloat16* src;
            uint32_t dst;
            if (c < 1024) {
                int mat = c >> 9;
                int cc = c & 511;
                int r = cc >> 2, col = (cc & 3) << 3;
                int gr = row0 + r;
                gr = gr < M ? gr : (M - 1);
                src = (mat ? Alo : Ahi) + (size_t)gr * KDIM + kc * 32 + col;
                dst = sb + mat * ABYTES + (uint32_t)(r * LDA + col) * 2;
            } else {
                int c2 = c - 1024;
                int mat = c2 / (BN_ * 4);
                int cc = c2 % (BN_ * 4);
                int r = cc >> 2, col = (cc & 3) << 3;
                src = (mat ? Blo : Bhi) + (size_t)(colBase + r) * KDIM + kc * 32 + col;
                dst = sb + BOFF + mat * BBYTES + (uint32_t)(r * LDA + col) * 2;
            }
            cpa16(dst, src);
        }
        cpa_commit();
    };

    load_stage(0, smBase);
    for (int kc = 0; kc < NC; kc++) {
        if (kc + 1 < NC) {
            load_stage(kc + 1, smBase + (uint32_t)((kc + 1) & 1) * SSTAGE);
            cpa_wait<1>();
        } else {
            cpa_wait<0>();
        }
        __syncthreads();
        uint32_t st = smBase + (uint32_t)(kc & 1) * SSTAGE;
        uint32_t uAhi = st, uAlo = st + ABYTES;
        uint32_t uBhi = st + BOFF, uBlo = st + BOFF + BBYTES;

#pragma unroll
        for (int ks = 0; ks < 2; ks++) {
            uint32_t ahi[2][4], alo[2][4];
#pragma unroll
            for (int mt = 0; mt < 2; mt++) {
                uint32_t aoff =
                    ((warpM * 32 + mt * 16 + (lane & 15)) * LDA + (lane >> 4) * 8 + ks * 16) * 2;
                ldsm4(ahi[mt], uAhi + aoff);
                ldsm4(alo[mt], uAlo + aoff);
            }
            uint32_t bhi[NT][2], blo[NT][2];
#pragma unroll
            for (int p = 0; p < NT / 2; p++) {
                int nrow = warpN * WN + p * 16 + (lane & 7) + ((lane & 16) >> 1);
                int kcol = ks * 16 + (lane & 8);
                uint32_t boff = (uint32_t)(nrow * LDA + kcol) * 2;
                uint32_t t[4];
                ldsm4(t, uBhi + boff);
                bhi[2 * p][0] = t[0]; bhi[2 * p][1] = t[1];
                bhi[2 * p + 1][0] = t[2]; bhi[2 * p + 1][1] = t[3];
                ldsm4(t, uBlo + boff);
                blo[2 * p][0] = t[0]; blo[2 * p][1] = t[1];
                blo[2 * p + 1][0] = t[2]; blo[2 * p + 1][1] = t[3];
            }
#pragma unroll
            for (int mt = 0; mt < 2; mt++)
#pragma unroll
                for (int nt = 0; nt < NT; nt++) {
                    mma16816(acc[mt][nt], ahi[mt], bhi[nt]);
                    mma16816(acc[mt][nt], ahi[mt], blo[nt]);
                    mma16816(acc[mt][nt], alo[mt], bhi[nt]);
                }
        }
        __syncthreads();
    }

    uint64_t pl = pol_evl();
#pragma unroll
    for (int mt = 0; mt < 2; mt++) {
        int row = row0 + warpM * 32 + mt * 16 + (lane >> 2);
#pragma unroll
        for (int nt = 0; nt < NT; nt++) {
            int col = colBase + warpN * WN + nt * 8 + (lane & 3) * 2;
            float b0 = 0.f, b1 = 0.f;
            if (bias) { b0 = bias[col]; b1 = bias[col + 1]; }
            float v0 = acc[mt][nt][0] + b0, v1 = acc[mt][nt][1] + b1;
            float v2 = acc[mt][nt][2] + b0, v3 = acc[mt][nt][3] + b1;
            if (ACT == 1) {
                v0 = v0 > 0.f ? v0 : SLOPE * v0; v1 = v1 > 0.f ? v1 : SLOPE * v1;
                v2 = v2 > 0.f ? v2 : SLOPE * v2; v3 = v3 > 0.f ? v3 : SLOPE * v3;
            }
            if (OSPLIT) {
                __nv_bfloat16 h0, l0, h1, l1;
                if (row < M) {
                    split_bf16(v0, h0, l0); split_bf16(v1, h1, l1);
                    __nv_bfloat16 hp[2] = {h0, h1}, lp[2] = {l0, l1};
                    stg_pol32(Chi + (size_t)row * NOUT + col, *(uint32_t*)hp, pl);
                    stg_pol32(Clo + (size_t)row * NOUT + col, *(uint32_t*)lp, pl);
                }
                if (row + 8 < M) {
                    split_bf16(v2, h0, l0); split_bf16(v3, h1, l1);
                    __nv_bfloat16 hp[2] = {h0, h1}, lp[2] = {l0, l1};
                    stg_pol32(Chi + (size_t)(row + 8) * NOUT + col, *(uint32_t*)hp, pl);
                    stg_pol32(Clo + (size_t)(row + 8) * NOUT + col, *(uint32_t*)lp, pl);
                }
            } else {
                if (row < M)
                    *(float2*)(C + (size_t)row * NOUT + col) = make_float2(v0, v1);
                if (row + 8 < M)
                    *(float2*)(C + (size_t)(row + 8) * NOUT + col) = make_float2(v2, v3);
            }
        }
    }
}

// ----------------------------------------------------------------------------
// Attention GEMM with fused sim epilogue
// ----------------------------------------------------------------------------
__global__ void __launch_bounds__(256, 2) hmma_att(
    const __nv_bfloat16* __restrict__ AhiB, const __nv_bfloat16* __restrict__ AloB,
    const __nv_bfloat16* __restrict__ BhiB, const __nv_bfloat16* __restrict__ BloB,
    const float* __restrict__ biasB, const float* __restrict__ qB,
    float* __restrict__ simB, int M)
{
    constexpr int LDA = 40, NC = 8;
    constexpr int ABYTES = 128 * LDA * 2;
    constexpr int BOFF = 2 * ABYTES;
    constexpr int BBYTES = 64 * LDA * 2;
    constexpr int SSTAGE = BOFF + 2 * BBYTES;
    extern __shared__ char dynsm[];
    uint32_t smBase = smem_u32(dynsm);

    int tid = threadIdx.x, wid = tid >> 5, lane = tid & 31;
    int row0 = blockIdx.x * 128;
    int kk = blockIdx.z;
    const __nv_bfloat16* Ahi = AhiB + (size_t)kk * NN * DD;
    const __nv_bfloat16* Alo = AloB + (size_t)kk * NN * DD;
    const __nv_bfloat16* Bhi = BhiB + (size_t)kk * 16384;
    const __nv_bfloat16* Blo = BloB + (size_t)kk * 16384;
    const float* bias = biasB + kk * ATTD;
    const float* q    = qB + kk * ATTD;
    float* sim        = simB + (size_t)kk * NN;

    float acc[8][4];
#pragma unroll
    for (int nt = 0; nt < 8; nt++)
#pragma unroll
        for (int p = 0; p < 4; p++) acc[nt][p] = 0.f;

    auto load_stage = [&](int kc, uint32_t sb) {
        constexpr int TOT = 1024 + 512;
#pragma unroll
        for (int c = tid; c < TOT; c += 256) {
            const __nv_bfloat16* src;
            uint32_t dst;
            if (c < 1024) {
                int mat = c >> 9;
                int cc = c & 511;
                int r = cc >> 2, col = (cc & 3) << 3;
                int gr = row0 + r;
                gr = gr < M ? gr : (M - 1);
                src = (mat ? Alo : Ahi) + (size_t)gr * DD + kc * 32 + col;
                dst = sb + mat * ABYTES + (uint32_t)(r * LDA + col) * 2;
            } else {
                int c2 = c - 1024;
                int mat = c2 >> 8;
                int cc = c2 & 255;
                int r = cc >> 2, col = (cc & 3) << 3;
                src = (mat ? Blo : Bhi) + (size_t)r * DD + kc * 32 + col;
                dst = sb + BOFF + mat * BBYTES + (uint32_t)(r * LDA + col) * 2;
            }
            cpa16(dst, src);
        }
        cpa_commit();
    };

    load_stage(0, smBase);
    for (int kc = 0; kc < NC; kc++) {
        if (kc + 1 < NC) {
            load_stage(kc + 1, smBase + (uint32_t)((kc + 1) & 1) * SSTAGE);
            cpa_wait<1>();
        } else {
            cpa_wait<0>();
        }
        __syncthreads();
        uint32_t st = smBase + (uint32_t)(kc & 1) * SSTAGE;
        uint32_t uAhi = st, uAlo = st + ABYTES;
        uint32_t uBhi = st + BOFF, uBlo = st + BOFF + BBYTES;

#pragma unroll
        for (int ks = 0; ks < 2; ks++) {
            uint32_t ahi[4], alo[4];
            uint32_t aoff =
                ((wid * 16 + (lane & 15)) * LDA + (lane >> 4) * 8 + ks * 16) * 2;
            ldsm4(ahi, uAhi + aoff);
            ldsm4(alo, uAlo + aoff);
            uint32_t bhi[8][2], blo[8][2];
#pragma unroll
            for (int p = 0; p < 4; p++) {
                int nrow = p * 16 + (lane & 7) + ((lane & 16) >> 1);
                int kcol = ks * 16 + (lane & 8);
                uint32_t boff = (uint32_t)(nrow * LDA + kcol) * 2;
                uint32_t t[4];
                ldsm4(t, uBhi + boff);
                bhi[2 * p][0] = t[0]; bhi[2 * p][1] = t[1];
                bhi[2 * p + 1][0] = t[2]; bhi[2 * p + 1][1] = t[3];
                ldsm4(t, uBlo + boff);
                blo[2 * p][0] = t[0]; blo[2 * p][1] = t[1];
                blo[2 * p + 1][0] = t[2]; blo[2 * p + 1][1] = t[3];
            }
#pragma unroll
            for (int nt = 0; nt < 8; nt++) {
                mma16816(acc[nt], ahi, bhi[nt]);
                mma16816(acc[nt], ahi, blo[nt]);
                mma16816(acc[nt], alo, bhi[nt]);
            }
        }
        __syncthreads();
    }

    float t0 = 0.f, t1 = 0.f;
#pragma unroll
    for (int nt = 0; nt < 8; nt++) {
        int col = nt * 8 + (lane & 3) * 2;
        float b0 = bias[col], b1 = bias[col + 1];
        float q0 = q[col], q1 = q[col + 1];
        t0 += tanhf(acc[nt][0] + b0) * q0 + tanhf(acc[nt][1] + b1) * q1;
        t1 += tanhf(acc[nt][2] + b0) * q0 + tanhf(acc[nt][3] + b1) * q1;
    }
    t0 += __shfl_xor_sync(0xffffffffu, t0, 1);
    t0 += __shfl_xor_sync(0xffffffffu, t0, 2);
    t1 += __shfl_xor_sync(0xffffffffu, t1, 1);
    t1 += __shfl_xor_sync(0xffffffffu, t1, 2);
    if ((lane & 3) == 0) {
        int row = row0 + wid * 16 + (lane >> 2);
        if (row < M) sim[row] = t0;
        if (row + 8 < M) sim[row + 8] = t1;
    }
}

// ----------------------------------------------------------------------------
// Softmax over K + combine + relu
// ----------------------------------------------------------------------------
__global__ void k_combine() {
    int node = (blockIdx.x * blockDim.x + threadIdx.x) >> 5;
    int lane = threadIdx.x & 31;
    if (node >= NN) return;
    uint64_t pl = pol_evl();
    uint64_t pf = pol_evf();
    float p0 = g_sim[node], p1 = g_sim[NN + node];
    float m = fmaxf(p0, p1);
    float e0 = expf(p0 - m), e1 = expf(p1 - m);
    float inv = 1.f / (e0 + e1);
    float a0v = e0 * inv, a1v = e1 * inv;
    size_t off = (size_t)node * DD + lane * 8;
    uint4 h0 = ldg_pol128(g_xshi + off, pf);
    uint4 l0 = ldg_pol128(g_xslo + off, pf);
    uint4 h1 = ldg_pol128(g_xshi + (size_t)NN * DD + off, pf);
    uint4 l1 = ldg_pol128(g_xslo + (size_t)NN * DD + off, pf);
    const __nv_bfloat16* ph0 = (const __nv_bfloat16*)&h0;
    const __nv_bfloat16* pl0 = (const __nv_bfloat16*)&l0;
    const __nv_bfloat16* ph1 = (const __nv_bfloat16*)&h1;
    const __nv_bfloat16* pl1 = (const __nv_bfloat16*)&l1;
    __nv_bfloat16 oh[8], ol[8];
#pragma unroll
    for (int j = 0; j < 8; j++) {
        float f0 = __bfloat162float(ph0[j]) + __bfloat162float(pl0[j]);
        float f1 = __bfloat162float(ph1[j]) + __bfloat162float(pl1[j]);
        float r = fmaxf(a0v * f0 + a1v * f1, 0.f);
        split_bf16(r, oh[j], ol[j]);
    }
    stg_pol128(g_hhi + off, *(uint4*)oh, pl);
    stg_pol128(g_hlo + off, *(uint4*)ol, pl);
}

// ----------------------------------------------------------------------------
// Host orchestration
// ----------------------------------------------------------------------------
extern "C" void kernel_launch(void* const* d_in, const int* in_sizes, int n_in,
                              void* d_out, int out_size) {
    const float* x     = (const float*)d_in[0];
    const int*   ei    = (const int*)d_in[1];
    const float* ew    = (const float*)d_in[2];
    const float* gamma = (const float*)d_in[3];
    const float* beta  = (const float*)d_in[4];
    const float* gcnW  = (const float*)d_in[5];
    const float* gcnb  = (const float*)d_in[6];
    const float* attW  = (const float*)d_in[7];
    const float* attb  = (const float*)d_in[8];
    const float* attq  = (const float*)d_in[9];
    const float* pW1   = (const float*)d_in[10];
    const float* pb1   = (const float*)d_in[11];
    const float* pW2   = (const float*)d_in[12];
    const float* pb2   = (const float*)d_in[13];

    float *pSim, *pXw;
    __nv_bfloat16 *pWhi, *pWlo, *pHhi, *pHlo, *pXshi, *pXslo, *pT1hi, *pT1lo;
    cudaGetSymbolAddress((void**)&pSim, g_sim);
    cudaGetSymbolAddress((void**)&pXw, g_xw);
    cudaGetSymbolAddress((void**)&pWhi, g_whi);
    cudaGetSymbolAddress((void**)&pWlo, g_wlo);
    cudaGetSymbolAddress((void**)&pHhi, g_hhi);
    cudaGetSymbolAddress((void**)&pHlo, g_hlo);
    cudaGetSymbolAddress((void**)&pXshi, g_xshi);
    cudaGetSymbolAddress((void**)&pXslo, g_xslo);
    cudaGetSymbolAddress((void**)&pT1hi, g_t1hi);
    cudaGetSymbolAddress((void**)&pT1lo, g_t1lo);

    cudaFuncSetAttribute((const void*)hmma_gemm<128, 256, 256, 0, 0>,
                         cudaFuncAttributeMaxDynamicSharedMemorySize, 81920);
    cudaFuncSetAttribute((const void*)hmma_att,
                         cudaFuncAttributeMaxDynamicSharedMemorySize, 61440);
    cudaFuncSetAttribute((const void*)hmma_gemm<128, 128, 256, 1, 1>,
                         cudaFuncAttributeMaxDynamicSharedMemorySize, 81920);
    cudaFuncSetAttribute((const void*)hmma_gemm<64, 64, 128, 1, 0>,
                         cudaFuncAttributeMaxDynamicSharedMemorySize, 61440);

    // Fused prologue
    k_pro0<<<NB_ZERO + NB_WSPL, 256>>>(gcnW, attW, pW1, pW2);
    k_pro1<<<NB_CSTAT + NB_DEG, 256>>>(x, ei, ew);
    k_pro2<<<NB_SCAN + 1, 1024>>>(gamma, beta);
    k_pro3<<<NB_SCAN + NB_BN, 1024>>>(x);
    k_scatter<<<(KE + 255) / 256, 256>>>(ei, ew);

    int nTiles = (NN + 127) / 128;

    for (int i = 0; i < LLn; i++) {
        // xw (fp32) = h @ gcn_W[i]
        hmma_gemm<128, 256, 256, 0, 0><<<dim3(nTiles, 2), 256, 81920>>>(
            pHhi, pHlo, pWhi + WOFF_GCN(i), pWlo + WOFF_GCN(i),
            nullptr, pXw, nullptr, nullptr, NN);
        k_aggregate<<<(KN + 7) / 8, 256>>>(gcnb + (size_t)i * DD);
        hmma_att<<<dim3(nTiles, 1, 2), 256, 61440>>>(
            pXshi, pXslo, pWhi + WOFF_ATT(i, 0), pWlo + WOFF_ATT(i, 0),
            attb + (size_t)i * KKk * ATTD, attq + (size_t)i * KKk * ATTD,
            pSim, NN);
        k_combine<<<(NN + 7) / 8, 256>>>();
    }

    hmma_gemm<128, 128, 256, 1, 1><<<dim3(nTiles, 1), 256, 81920>>>(
        pHhi, pHlo, pWhi + WOFF_P1, pWlo + WOFF_P1, pb1, nullptr, pT1hi, pT1lo, NN);
    hmma_gemm<64, 64, 128, 1, 0><<<dim3(nTiles, 1), 256, 61440>>>(
        pT1hi, pT1lo, pWhi + WOFF_P2, pWlo + WOFF_P2, pb2, (float*)d_out,
        nullptr, nullptr, NN);
}